// round 12
// baseline (speedup 1.0000x reference)
#include <cuda_runtime.h>
#include <cuda_fp16.h>
#include <cstdint>
#include <math.h>

// ---------------- problem constants ----------------
#define BB   8
#define SS   512
#define DD   768
#define HH   12
#define DH   64
#define EE   14
#define KK   4
#define HID  1536
#define SHH  3072
#define NTOK (BB*SS)          // 4096
#define BHN  (BB*HH)          // 96

// ---------------- scratch (device globals; no allocation) ----------------
__device__ __align__(128) __half g_h1h [(size_t)NTOK*DD];
__device__ __align__(128) __half g_qh  [(size_t)BHN*SS*DH];
__device__ __align__(128) __half g_kh  [(size_t)BHN*SS*DH];
__device__ __align__(128) __half g_vh  [(size_t)BHN*SS*DH];
__device__ __align__(128) __half g_aoh [(size_t)NTOK*DD];
__device__ __align__(128) float  g_x2  [(size_t)NTOK*DD];
__device__ __align__(128) float  g_h2f [(size_t)NTOK*DD];
__device__ __align__(128) __half g_h2h [(size_t)NTOK*DD];
__device__ __align__(128) float  g_seq [(size_t)BB*DD];
__device__ __align__(128) float  g_wgt [(size_t)BB*EE];
__device__ __align__(128) __half g_ehidh[(size_t)EE*BB*SS*HID];
__device__ __align__(128) __half g_shidh[(size_t)NTOK*SHH];
__device__ __align__(128) float  g_part[3][(size_t)NTOK*DD];   // 0 experts, 1..2 final splits
// fp16 weight mirrors, [K][N] row-major
__device__ __align__(128) __half g_qkvw_h [(size_t)DD*3*DD];
__device__ __align__(128) __half g_projw_h[(size_t)DD*DD];
__device__ __align__(128) __half g_shw1_h [(size_t)DD*SHH];
__device__ __align__(128) __half g_shw2_h [(size_t)SHH*DD];
__device__ __align__(128) __half g_expw1_h[(size_t)EE*DD*HID];
__device__ __align__(128) __half g_expw2_h[(size_t)EE*HID*DD];

// ---------------- helpers ----------------
__device__ __forceinline__ float geluf(float x) {
    return 0.5f * x * (1.0f + erff(x * 0.70710678118654752f));
}
__device__ __forceinline__ uint32_t packh2(float a, float b) {
    __half2 h = __floats2half2_rn(a, b);
    return *(uint32_t*)&h;
}
__device__ __forceinline__ void cp16h(__half* dst_smem, const __half* src) {
    uint32_t d = (uint32_t)__cvta_generic_to_shared(dst_smem);
    asm volatile("cp.async.cg.shared.global [%0], [%1], 16;" :: "r"(d), "l"(src));
}
__device__ __forceinline__ void ldsm4(uint32_t &r0, uint32_t &r1, uint32_t &r2, uint32_t &r3,
                                      uint32_t addr) {
    asm volatile("ldmatrix.sync.aligned.m8n8.x4.shared.b16 {%0,%1,%2,%3}, [%4];"
                 : "=r"(r0), "=r"(r1), "=r"(r2), "=r"(r3) : "r"(addr));
}
__device__ __forceinline__ void ldsm4t(uint32_t &r0, uint32_t &r1, uint32_t &r2, uint32_t &r3,
                                       uint32_t addr) {
    asm volatile("ldmatrix.sync.aligned.m8n8.x4.trans.shared.b16 {%0,%1,%2,%3}, [%4];"
                 : "=r"(r0), "=r"(r1), "=r"(r2), "=r"(r3) : "r"(addr));
}
__device__ __forceinline__ void mma_f16(float c[4], const uint32_t a[4], const uint32_t b[2]) {
    asm volatile("mma.sync.aligned.m16n8k16.row.col.f32.f16.f16.f32 "
                 "{%0,%1,%2,%3}, {%4,%5,%6,%7}, {%8,%9}, {%0,%1,%2,%3};"
                 : "+f"(c[0]), "+f"(c[1]), "+f"(c[2]), "+f"(c[3])
                 : "r"(a[0]), "r"(a[1]), "r"(a[2]), "r"(a[3]), "r"(b[0]), "r"(b[1]));
}

__device__ __forceinline__ float blockReduceSum(float v, float* sh) {
    int tid = threadIdx.x;
    sh[tid] = v; __syncthreads();
    for (int s = 128; s > 0; s >>= 1) {
        if (tid < s) sh[tid] += sh[tid + s];
        __syncthreads();
    }
    float r = sh[0]; __syncthreads();
    return r;
}

// ======================================================================
// fp16 GEMM core: 128 threads / 4 warps, warp tile 64x64, CTA 128x128,
// BK=64, 3-stage cp.async, one barrier per 64 k-elements, register
// double-buffered fragments. acc accumulates across calls.
// ======================================================================
#define G2_LDA 72
#define G2_LDB 136
#define G2_ASZ (128*G2_LDA)
#define G2_BSZ (64*G2_LDB)
#define G2_STG (G2_ASZ + G2_BSZ)          // 17920 halves = 35840 B
#define SMEMB_G2 (3 * G2_STG * 2)         // 107520 B

__device__ __forceinline__ void gemm2(const __half* __restrict__ A, int lda,
                                      const __half* __restrict__ B, int ldb,
                                      int K, __half* smem, float acc[4][8][4])
{
    const int tid  = threadIdx.x;         // 128
    const int lane = tid & 31;
    const int w    = tid >> 5;
    const int wm   = w >> 1;
    const int wn   = w & 1;
    const int l16  = lane & 15;
    const int lh   = lane >> 4;

#define G2_LOAD(kt, stg)                                                     \
    { __half* bA = smem + (stg) * G2_STG;                                    \
      __half* bBp = bA + G2_ASZ;                                             \
      _Pragma("unroll")                                                      \
      for (int i = 0; i < 8; i++) {                                          \
          int e = tid + i * 128; int row = e >> 3, v = e & 7;                \
          cp16h(bA + row * G2_LDA + v * 8, A + (size_t)row * lda + (kt) + v * 8); } \
      _Pragma("unroll")                                                      \
      for (int i = 0; i < 8; i++) {                                          \
          int e = tid + i * 128; int row = e >> 4, v = e & 15;               \
          cp16h(bBp + row * G2_LDB + v * 8, B + (size_t)((kt) + row) * ldb + v * 8); } }

#define G2_FRAG(kk, buf, aB, bBa)                                            \
    { int k0 = (kk) * 16;                                                    \
      _Pragma("unroll")                                                      \
      for (int mt = 0; mt < 4; mt++)                                         \
          ldsm4(a[buf][mt][0], a[buf][mt][1], a[buf][mt][2], a[buf][mt][3],  \
                (aB) + 2u * ((wm * 64 + mt * 16 + l16) * G2_LDA + k0 + lh * 8)); \
      _Pragma("unroll")                                                      \
      for (int p = 0; p < 4; p++) {                                          \
          uint32_t r0, r1, r2, r3;                                           \
          ldsm4t(r0, r1, r2, r3,                                             \
                 (bBa) + 2u * ((k0 + l16) * G2_LDB + wn * 64 + p * 16 + lh * 8)); \
          b[buf][2 * p][0] = r0; b[buf][2 * p][1] = r1;                      \
          b[buf][2 * p + 1][0] = r2; b[buf][2 * p + 1][1] = r3; } }

    const int nst = K / 64;
    G2_LOAD(0, 0);
    asm volatile("cp.async.commit_group;");
    G2_LOAD(64, 1);
    asm volatile("cp.async.commit_group;");

    uint32_t a[2][4][4], b[2][8][2];

    int stg = 0;
    for (int t = 0; t < nst; t++) {
        if (t + 1 < nst) asm volatile("cp.async.wait_group 1;" ::: "memory");
        else             asm volatile("cp.async.wait_group 0;" ::: "memory");
        __syncthreads();
        if (t + 2 < nst) {
            int ns = stg + 2; if (ns >= 3) ns -= 3;
            G2_LOAD((t + 2) * 64, ns);
            asm volatile("cp.async.commit_group;");
        }
        __half* cA = smem + stg * G2_STG;
        uint32_t aB = (uint32_t)__cvta_generic_to_shared(cA);
        uint32_t bBa = (uint32_t)__cvta_generic_to_shared(cA + G2_ASZ);

        G2_FRAG(0, 0, aB, bBa);
#pragma unroll
        for (int kk = 0; kk < 4; kk++) {
            if (kk < 3) G2_FRAG(kk + 1, (kk + 1) & 1, aB, bBa);
#pragma unroll
            for (int mt = 0; mt < 4; mt++)
#pragma unroll
                for (int nt = 0; nt < 8; nt++)
                    mma_f16(acc[mt][nt], a[kk & 1][mt], b[kk & 1][nt]);
        }
        if (++stg == 3) stg = 0;
    }
    __syncthreads();
#undef G2_LOAD
#undef G2_FRAG
}

#define EPI2_SETUP()                                            \
    const int tid = threadIdx.x;                                \
    const int lane = tid & 31, w = tid >> 5;                    \
    const int wm = w >> 1, wn = w & 1;                          \
    const int g = lane >> 2, tig = lane & 3;

// ---------------- gemm2 kernels (128 threads each) ----------------

__global__ void __launch_bounds__(128) qkv_g2()
{
    extern __shared__ __half smem[];
    int row0 = blockIdx.y * 128, col0 = blockIdx.x * 128;
    float acc[4][8][4] = {};
    gemm2(g_h1h + (size_t)row0 * DD, DD, g_qkvw_h + col0, 3 * DD, DD, smem, acc);
    EPI2_SETUP();
#pragma unroll
    for (int mt = 0; mt < 4; mt++)
#pragma unroll
        for (int nt = 0; nt < 8; nt++) {
            int n = col0 + wn * 64 + nt * 8 + 2 * tig;
            int which = n / DD;
            int rem = n - which * DD;
            int h = rem >> 6, d = rem & 63;
            __half* dst = (which == 0) ? g_qh : ((which == 1) ? g_kh : g_vh);
#pragma unroll
            for (int hf = 0; hf < 2; hf++) {
                int m = row0 + wm * 64 + mt * 16 + g + hf * 8;
                int b = m >> 9, s = m & 511;
                *(__half2*)&dst[(((size_t)b * HH + h) * SS + s) * DH + d] =
                    __floats2half2_rn(acc[mt][nt][2 * hf], acc[mt][nt][2 * hf + 1]);
            }
        }
}

__global__ void __launch_bounds__(128) proj_g2(const float* __restrict__ bias,
                                               const float* __restrict__ x)
{
    extern __shared__ __half smem[];
    int row0 = blockIdx.y * 128, col0 = blockIdx.x * 128;
    float acc[4][8][4] = {};
    gemm2(g_aoh + (size_t)row0 * DD, DD, g_projw_h + col0, DD, DD, smem, acc);
    EPI2_SETUP();
#pragma unroll
    for (int mt = 0; mt < 4; mt++)
#pragma unroll
        for (int nt = 0; nt < 8; nt++) {
            int n = col0 + wn * 64 + nt * 8 + 2 * tig;
            float b0 = bias[n], b1 = bias[n + 1];
#pragma unroll
            for (int hf = 0; hf < 2; hf++) {
                int m = row0 + wm * 64 + mt * 16 + g + hf * 8;
                size_t idx = (size_t)m * DD + n;
                float2 xv = *(const float2*)&x[idx];
                *(float2*)&g_x2[idx] =
                    make_float2(xv.x + acc[mt][nt][2 * hf] + b0,
                                xv.y + acc[mt][nt][2 * hf + 1] + b1);
            }
        }
}

// expert hidden, slot-parallel (z = b*KK + slot, 32 slices, all active)
__global__ void __launch_bounds__(128) expert_hid_g2(const float* __restrict__ b1)
{
    extern __shared__ __half smem[];
    int b = blockIdx.z >> 2, slot = blockIdx.z & 3;
    int e = 0; float wv = 0.0f;
    {
        int cnt = -1;
        for (int j = 0; j < EE; j++) {
            float t = g_wgt[b * EE + j];
            if (t != 0.0f) { cnt++; if (cnt == slot) { e = j; wv = t; break; } }
        }
    }
    int row0 = blockIdx.y * 128, col0 = blockIdx.x * 128;
    float acc[4][8][4] = {};
    gemm2(g_h2h + ((size_t)b * SS + row0) * DD, DD,
          g_expw1_h + (size_t)e * DD * HID + col0, HID, DD, smem, acc);
    EPI2_SETUP();
    __half* dst = g_ehidh + ((size_t)e * BB + b) * SS * HID;
#pragma unroll
    for (int mt = 0; mt < 4; mt++)
#pragma unroll
        for (int nt = 0; nt < 8; nt++) {
            int n = col0 + wn * 64 + nt * 8 + 2 * tig;
            float b0 = b1[e * HID + n], bx = b1[e * HID + n + 1];
#pragma unroll
            for (int hf = 0; hf < 2; hf++) {
                int m = row0 + wm * 64 + mt * 16 + g + hf * 8;
                *(__half2*)&dst[(size_t)m * HID + n] =
                    __floats2half2_rn(wv * geluf(acc[mt][nt][2 * hf] + b0),
                                      wv * geluf(acc[mt][nt][2 * hf + 1] + bx));
            }
        }
}

// expert out: one block per (tile, b); accumulates ALL 4 active experts
// in-register (ehid already wv-scaled), writes single partial g_part[0].
__global__ void __launch_bounds__(128) expert_out_g2(const float* __restrict__ b2)
{
    extern __shared__ __half smem[];
    int b = blockIdx.z;
    int row0 = blockIdx.y * 128, col0 = blockIdx.x * 128;
    float acc[4][8][4] = {};
    int eidx[KK]; float wvv[KK];
    {
        int cnt = 0;
        for (int j = 0; j < EE; j++) {
            float t = g_wgt[b * EE + j];
            if (t != 0.0f) { eidx[cnt] = j; wvv[cnt] = t; cnt++; }
        }
    }
#pragma unroll 1
    for (int s = 0; s < KK; s++) {
        int e = eidx[s];
        gemm2(g_ehidh + (((size_t)e * BB + b) * SS + row0) * HID, HID,
              g_expw2_h + (size_t)e * HID * DD + col0, DD, HID, smem, acc);
    }
    EPI2_SETUP();
    float* dst = g_part[0];
#pragma unroll
    for (int mt = 0; mt < 4; mt++)
#pragma unroll
        for (int nt = 0; nt < 8; nt++) {
            int n = col0 + wn * 64 + nt * 8 + 2 * tig;
            float b0 = 0.0f, b1v = 0.0f;
#pragma unroll
            for (int s = 0; s < KK; s++) {
                b0  += wvv[s] * b2[eidx[s] * DD + n];
                b1v += wvv[s] * b2[eidx[s] * DD + n + 1];
            }
#pragma unroll
            for (int hf = 0; hf < 2; hf++) {
                int m = row0 + wm * 64 + mt * 16 + g + hf * 8;
                *(float2*)&dst[((size_t)b * SS + m) * DD + n] =
                    make_float2(acc[mt][nt][2 * hf] + b0,
                                acc[mt][nt][2 * hf + 1] + b1v);
            }
        }
}

__global__ void __launch_bounds__(128) shared_hid_g2(const float* __restrict__ b1)
{
    extern __shared__ __half smem[];
    int row0 = blockIdx.y * 128, col0 = blockIdx.x * 128;
    float acc[4][8][4] = {};
    gemm2(g_h2h + (size_t)row0 * DD, DD, g_shw1_h + col0, SHH, DD, smem, acc);
    EPI2_SETUP();
#pragma unroll
    for (int mt = 0; mt < 4; mt++)
#pragma unroll
        for (int nt = 0; nt < 8; nt++) {
            int n = col0 + wn * 64 + nt * 8 + 2 * tig;
            float b0 = b1[n], bx = b1[n + 1];
#pragma unroll
            for (int hf = 0; hf < 2; hf++) {
                int m = row0 + wm * 64 + mt * 16 + g + hf * 8;
                *(__half2*)&g_shidh[(size_t)m * SHH + n] =
                    __floats2half2_rn(geluf(acc[mt][nt][2 * hf] + b0),
                                      geluf(acc[mt][nt][2 * hf + 1] + bx));
            }
        }
}

// final split-K chunk c (2 chunks of K=1536): g_part[1+c]
__global__ void __launch_bounds__(128) final_split_g2()
{
    extern __shared__ __half smem[];
    int c = blockIdx.z;
    int row0 = blockIdx.y * 128, col0 = blockIdx.x * 128;
    float acc[4][8][4] = {};
    gemm2(g_shidh + (size_t)row0 * SHH + c * 1536, SHH,
          g_shw2_h + (size_t)(c * 1536) * DD + col0, DD, 1536, smem, acc);
    EPI2_SETUP();
    float* dst = g_part[1 + c];
#pragma unroll
    for (int mt = 0; mt < 4; mt++)
#pragma unroll
        for (int nt = 0; nt < 8; nt++) {
            int n = col0 + wn * 64 + nt * 8 + 2 * tig;
#pragma unroll
            for (int hf = 0; hf < 2; hf++) {
                int m = row0 + wm * 64 + mt * 16 + g + hf * 8;
                *(float2*)&dst[(size_t)m * DD + n] =
                    make_float2(acc[mt][nt][2 * hf], acc[mt][nt][2 * hf + 1]);
            }
        }
}

// ---------------- flash attention (fp16, P in registers) ----------------
#define FLDA 72
#define FLASH_SMEM (3 * 128 * FLDA * 2)

__global__ void __launch_bounds__(256, 1) flash_tc()
{
    extern __shared__ __half hsm[];
    __half* sQ = hsm;
    __half* sK = hsm + 128 * FLDA;
    __half* sV = hsm + 2 * 128 * FLDA;

    const int bh = blockIdx.y;
    const int q0 = blockIdx.x * 128;
    const __half* Qg = g_qh + ((size_t)bh * SS + q0) * DH;
    const __half* Kg = g_kh + (size_t)bh * SS * DH;
    const __half* Vg = g_vh + (size_t)bh * SS * DH;

    const int tid = threadIdx.x, lane = tid & 31, w = tid >> 5;
    const int l16 = lane & 15, lh = lane >> 4;
    const int g = lane >> 2, tig = lane & 3;

#define FCOPY(dst, src)                                                       \
    { _Pragma("unroll")                                                       \
      for (int i = 0; i < 4; i++) {                                           \
          int e = tid + i * 256; int r = e >> 3, v = e & 7;                   \
          cp16h((dst) + r * FLDA + v * 8, (src) + (size_t)r * 64 + v * 8); } }

    FCOPY(sQ, Qg);
    FCOPY(sK, Kg);
    asm volatile("cp.async.commit_group;");
    FCOPY(sV, Vg);
    asm volatile("cp.async.commit_group;");

    float acc_o[8][4] = {};
    float mrun[2] = {-1e30f, -1e30f};
    float lrun[2] = {0.0f, 0.0f};

    const uint32_t sQa = (uint32_t)__cvta_generic_to_shared(sQ);
    const uint32_t sKa = (uint32_t)__cvta_generic_to_shared(sK);
    const uint32_t sVa = (uint32_t)__cvta_generic_to_shared(sV);

    for (int st = 0; st < 4; st++) {
        asm volatile("cp.async.wait_group 1;" ::: "memory");
        __syncthreads();

        float s[16][4] = {};
#pragma unroll
        for (int kk = 0; kk < 4; kk++) {
            int k0 = kk * 16;
            uint32_t a[4];
            ldsm4(a[0], a[1], a[2], a[3],
                  sQa + 2u * ((w * 16 + l16) * FLDA + k0 + lh * 8));
#pragma unroll
            for (int p = 0; p < 8; p++) {
                uint32_t r0, r1, r2, r3;
                ldsm4(r0, r1, r2, r3,
                      sKa + 2u * ((p * 16 + l16) * FLDA + k0 + lh * 8));
                uint32_t b0[2] = {r0, r2}, b1[2] = {r1, r3};
                mma_f16(s[2 * p], a, b0);
                mma_f16(s[2 * p + 1], a, b1);
            }
        }

        float tmax[2] = {-1e30f, -1e30f};
#pragma unroll
        for (int nt = 0; nt < 16; nt++) {
            tmax[0] = fmaxf(tmax[0], fmaxf(s[nt][0], s[nt][1]));
            tmax[1] = fmaxf(tmax[1], fmaxf(s[nt][2], s[nt][3]));
        }
#pragma unroll
        for (int o = 1; o < 4; o <<= 1) {
            tmax[0] = fmaxf(tmax[0], __shfl_xor_sync(0xffffffffu, tmax[0], o));
            tmax[1] = fmaxf(tmax[1], __shfl_xor_sync(0xffffffffu, tmax[1], o));
        }
        float mnew[2], corr[2], rsum[2] = {0.0f, 0.0f};
#pragma unroll
        for (int h = 0; h < 2; h++) {
            mnew[h] = fmaxf(mrun[h], tmax[h] * 0.125f);
            corr[h] = __expf(mrun[h] - mnew[h]);
            mrun[h] = mnew[h];
        }
        uint32_t ph[16][2];
#pragma unroll
        for (int nt = 0; nt < 16; nt++) {
            float p0 = __expf(s[nt][0] * 0.125f - mnew[0]);
            float p1 = __expf(s[nt][1] * 0.125f - mnew[0]);
            float p2 = __expf(s[nt][2] * 0.125f - mnew[1]);
            float p3 = __expf(s[nt][3] * 0.125f - mnew[1]);
            rsum[0] += p0 + p1; rsum[1] += p2 + p3;
            ph[nt][0] = packh2(p0, p1);
            ph[nt][1] = packh2(p2, p3);
        }
#pragma unroll
        for (int o = 1; o < 4; o <<= 1) {
            rsum[0] += __shfl_xor_sync(0xffffffffu, rsum[0], o);
            rsum[1] += __shfl_xor_sync(0xffffffffu, rsum[1], o);
        }
        lrun[0] = lrun[0] * corr[0] + rsum[0];
        lrun[1] = lrun[1] * corr[1] + rsum[1];
#pragma unroll
        for (int nt = 0; nt < 8; nt++) {
            acc_o[nt][0] *= corr[0]; acc_o[nt][1] *= corr[0];
            acc_o[nt][2] *= corr[1]; acc_o[nt][3] *= corr[1];
        }

        asm volatile("cp.async.wait_group 0;" ::: "memory");
        __syncthreads();
        if (st < 3) {
            FCOPY(sK, Kg + (size_t)(st + 1) * 128 * 64);
            asm volatile("cp.async.commit_group;");
        }

#pragma unroll
        for (int j = 0; j < 8; j++) {
            int k0 = j * 16;
            uint32_t a[4] = {ph[2 * j][0], ph[2 * j][1], ph[2 * j + 1][0], ph[2 * j + 1][1]};
#pragma unroll
            for (int p = 0; p < 4; p++) {
                uint32_t r0, r1, r2, r3;
                ldsm4t(r0, r1, r2, r3,
                       sVa + 2u * ((k0 + l16) * FLDA + p * 16 + lh * 8));
                uint32_t b0[2] = {r0, r1}, b1[2] = {r2, r3};
                mma_f16(acc_o[2 * p], a, b0);
                mma_f16(acc_o[2 * p + 1], a, b1);
            }
        }
        __syncthreads();
        if (st < 3) {
            FCOPY(sV, Vg + (size_t)(st + 1) * 128 * 64);
            asm volatile("cp.async.commit_group;");
        }
    }

    const int b = bh / HH, hh = bh - b * HH;
    const float inv0 = 1.0f / lrun[0], inv1 = 1.0f / lrun[1];
    const int m0 = q0 + w * 16 + g;
#pragma unroll
    for (int nt = 0; nt < 8; nt++) {
        int d = nt * 8 + 2 * tig;
        *(__half2*)&g_aoh[((size_t)b * SS + m0) * DD + hh * DH + d] =
            __floats2half2_rn(acc_o[nt][0] * inv0, acc_o[nt][1] * inv0);
        *(__half2*)&g_aoh[((size_t)b * SS + m0 + 8) * DD + hh * DH + d] =
            __floats2half2_rn(acc_o[nt][2] * inv1, acc_o[nt][3] * inv1);
    }
#undef FCOPY
}

// ---------------- conversion kernels ----------------
__global__ void f2h_kernel(const float* __restrict__ in, __half* __restrict__ out, int n8)
{
    int i = blockIdx.x * 256 + threadIdx.x;
    if (i >= n8) return;
    float4 a = ((const float4*)in)[2 * i];
    float4 b = ((const float4*)in)[2 * i + 1];
    uint4 u;
    u.x = packh2(a.x, a.y); u.y = packh2(a.z, a.w);
    u.z = packh2(b.x, b.y); u.w = packh2(b.z, b.w);
    ((uint4*)out)[i] = u;
}

__global__ void expconv_kernel(const float* __restrict__ w1, const float* __restrict__ w2)
{
    int e = blockIdx.y;
    int i = blockIdx.x * 256 + threadIdx.x;
    const int n8 = DD * HID / 8;
    const float* src; __half* dst; int j;
    if (i < n8) { src = w1 + (size_t)e * DD * HID; dst = g_expw1_h + (size_t)e * DD * HID; j = i; }
    else        { src = w2 + (size_t)e * HID * DD; dst = g_expw2_h + (size_t)e * HID * DD; j = i - n8; }
    float4 a = ((const float4*)src)[2 * j];
    float4 b = ((const float4*)src)[2 * j + 1];
    uint4 u;
    u.x = packh2(a.x, a.y); u.y = packh2(a.z, a.w);
    u.z = packh2(b.x, b.y); u.w = packh2(b.z, b.w);
    ((uint4*)dst)[j] = u;
}

// ---------------- elementwise kernels ----------------
__global__ void ln_kernel(const float* __restrict__ in, const float* __restrict__ g,
                          const float* __restrict__ b, __half* __restrict__ outh,
                          float* __restrict__ outf)
{
    __shared__ float red[256];
    size_t row = blockIdx.x;
    const float* xr = in + row * DD;
    int tid = threadIdx.x;
    float x0 = xr[tid], x1 = xr[tid + 256], x2 = xr[tid + 512];
    float total = blockReduceSum(x0 + x1 + x2, red);
    float mean = total * (1.0f / DD);
    float d0 = x0 - mean, d1 = x1 - mean, d2 = x2 - mean;
    float var = blockReduceSum(d0 * d0 + d1 * d1 + d2 * d2, red) * (1.0f / DD);
    float rstd = rsqrtf(var + 1e-5f);
    float r0 = d0 * rstd * g[tid]       + b[tid];
    float r1 = d1 * rstd * g[tid + 256] + b[tid + 256];
    float r2 = d2 * rstd * g[tid + 512] + b[tid + 512];
    outh[row * DD + tid]       = __float2half_rn(r0);
    outh[row * DD + tid + 256] = __float2half_rn(r1);
    outh[row * DD + tid + 512] = __float2half_rn(r2);
    if (outf) {
        outf[row * DD + tid]       = r0;
        outf[row * DD + tid + 256] = r1;
        outf[row * DD + tid + 512] = r2;
    }
}

__global__ void seqmean_kernel()
{
    int b = blockIdx.y;
    int d = blockIdx.x * 256 + threadIdx.x;
    const float* p = g_h2f + (size_t)b * SS * DD + d;
    float s = 0.0f;
    for (int i = 0; i < SS; i++) s += p[(size_t)i * DD];
    g_seq[b * DD + d] = s * (1.0f / SS);
}

__global__ void router_kernel(const float* __restrict__ w1, const float* __restrict__ b1,
                              const float* __restrict__ w2, const float* __restrict__ b2)
{
    __shared__ float s_in[DD];
    __shared__ float s_hid[DD];
    __shared__ float s_logits[EE];
    int b = blockIdx.x;
    int tid = threadIdx.x;
    for (int i = tid; i < DD; i += 256) s_in[i] = g_seq[b * DD + i];
    __syncthreads();
    for (int j = tid; j < DD; j += 256) {
        float a = b1[j];
        for (int d = 0; d < DD; d++) a = fmaf(s_in[d], w1[(size_t)d * DD + j], a);
        s_hid[j] = geluf(a);
    }
    __syncthreads();
    if (tid < EE) {
        float a = b2[tid];
        for (int d = 0; d < DD; d++) a = fmaf(s_hid[d], w2[(size_t)d * EE + tid], a);
        s_logits[tid] = a;
    }
    __syncthreads();
    if (tid == 0) {
        float p[EE];
        float mx = -1e30f;
        for (int e = 0; e < EE; e++) mx = fmaxf(mx, s_logits[e]);
        float sum = 0.0f;
        for (int e = 0; e < EE; e++) { p[e] = expf(s_logits[e] - mx); sum += p[e]; }
        float inv = 1.0f / sum;
        for (int e = 0; e < EE; e++) p[e] *= inv;
        int   idx[KK];
        float val[KK];
        bool used[EE] = {};
        for (int k = 0; k < KK; k++) {
            int best = -1; float bv = -1e30f;
            for (int e = 0; e < EE; e++)
                if (!used[e] && p[e] > bv) { bv = p[e]; best = e; }
            used[best] = true; idx[k] = best; val[k] = bv;
        }
        float m2 = val[0];
        float s2 = 0.0f, tw[KK];
        for (int k = 0; k < KK; k++) { tw[k] = expf(val[k] - m2); s2 += tw[k]; }
        float inv2 = 1.0f / s2;
        for (int e = 0; e < EE; e++) g_wgt[b * EE + e] = 0.0f;
        for (int k = 0; k < KK; k++) g_wgt[b * EE + idx[k]] = tw[k] * inv2;
    }
}

__global__ void final_sum_kernel(const float* __restrict__ b2, float* __restrict__ out)
{
    int i = blockIdx.x * 256 + threadIdx.x;
    int n = (i % (DD / 4)) * 4;
    float4 r = *(const float4*)(g_x2 + (size_t)i * 4);
#pragma unroll
    for (int j = 0; j < 3; j++) {
        float4 p = *(const float4*)(g_part[j] + (size_t)i * 4);
        r.x += p.x; r.y += p.y; r.z += p.z; r.w += p.w;
    }
    float4 bb = *(const float4*)(b2 + n);
    r.x += bb.x; r.y += bb.y; r.z += bb.z; r.w += bb.w;
    *(float4*)(out + (size_t)i * 4) = r;
}

// ---------------- launch ----------------
extern "C" void kernel_launch(void* const* d_in, const int* in_sizes, int n_in,
                              void* d_out, int out_size)
{
    const float* x         = (const float*)d_in[0];
    const float* ln1_g     = (const float*)d_in[1];
    const float* ln1_b     = (const float*)d_in[2];
    const float* qkv_w     = (const float*)d_in[3];
    const float* proj_w    = (const float*)d_in[4];
    const float* proj_b    = (const float*)d_in[5];
    const float* ln2_g     = (const float*)d_in[6];
    const float* ln2_b     = (const float*)d_in[7];
    const float* router_w1 = (const float*)d_in[8];
    const float* router_b1 = (const float*)d_in[9];
    const float* router_w2 = (const float*)d_in[10];
    const float* router_b2 = (const float*)d_in[11];
    const float* exp_w1    = (const float*)d_in[12];
    const float* exp_b1    = (const float*)d_in[13];
    const float* exp_w2    = (const float*)d_in[14];
    const float* exp_b2    = (const float*)d_in[15];
    const float* sh_w1     = (const float*)d_in[16];
    const float* sh_b1     = (const float*)d_in[17];
    const float* sh_w2     = (const float*)d_in[18];
    const float* sh_b2     = (const float*)d_in[19];
    float* out = (float*)d_out;

    static cudaStream_t sW = nullptr, sB = nullptr;
    static cudaEvent_t evF1 = nullptr, evW = nullptr, evWX = nullptr,
                       evF2 = nullptr, evB = nullptr;
    if (!sW) {
        cudaStreamCreateWithFlags(&sW, cudaStreamNonBlocking);
        cudaStreamCreateWithFlags(&sB, cudaStreamNonBlocking);
        cudaEventCreateWithFlags(&evF1, cudaEventDisableTiming);
        cudaEventCreateWithFlags(&evW,  cudaEventDisableTiming);
        cudaEventCreateWithFlags(&evWX, cudaEventDisableTiming);
        cudaEventCreateWithFlags(&evF2, cudaEventDisableTiming);
        cudaEventCreateWithFlags(&evB,  cudaEventDisableTiming);
    }

    cudaFuncSetAttribute(qkv_g2,        cudaFuncAttributeMaxDynamicSharedMemorySize, SMEMB_G2);
    cudaFuncSetAttribute(proj_g2,       cudaFuncAttributeMaxDynamicSharedMemorySize, SMEMB_G2);
    cudaFuncSetAttribute(expert_hid_g2, cudaFuncAttributeMaxDynamicSharedMemorySize, SMEMB_G2);
    cudaFuncSetAttribute(expert_out_g2, cudaFuncAttributeMaxDynamicSharedMemorySize, SMEMB_G2);
    cudaFuncSetAttribute(shared_hid_g2, cudaFuncAttributeMaxDynamicSharedMemorySize, SMEMB_G2);
    cudaFuncSetAttribute(final_split_g2,cudaFuncAttributeMaxDynamicSharedMemorySize, SMEMB_G2);
    cudaFuncSetAttribute(flash_tc,      cudaFuncAttributeMaxDynamicSharedMemorySize, FLASH_SMEM);

    __half* wq;  cudaGetSymbolAddress((void**)&wq,  g_qkvw_h);
    __half* wp;  cudaGetSymbolAddress((void**)&wp,  g_projw_h);
    __half* w1;  cudaGetSymbolAddress((void**)&w1,  g_shw1_h);
    __half* w2;  cudaGetSymbolAddress((void**)&w2,  g_shw2_h);
    __half* h1h; cudaGetSymbolAddress((void**)&h1h, g_h1h);
    __half* h2h; cudaGetSymbolAddress((void**)&h2h, g_h2h);
    float*  h2f; cudaGetSymbolAddress((void**)&h2f, g_h2f);
    float*  x2;  cudaGetSymbolAddress((void**)&x2,  g_x2);

    // fork sW: weight conversions (attn/shared first, then all experts)
    cudaEventRecord(evF1, 0);
    cudaStreamWaitEvent(sW, evF1, 0);
    f2h_kernel<<<(DD*3*DD/8 + 255)/256, 256, 0, sW>>>(qkv_w, wq, DD*3*DD/8);
    f2h_kernel<<<(DD*DD/8   + 255)/256, 256, 0, sW>>>(proj_w, wp, DD*DD/8);
    f2h_kernel<<<(DD*SHH/8  + 255)/256, 256, 0, sW>>>(sh_w1, w1, DD*SHH/8);
    f2h_kernel<<<(SHH*DD/8  + 255)/256, 256, 0, sW>>>(sh_w2, w2, SHH*DD/8);
    cudaEventRecord(evW, sW);
    expconv_kernel<<<dim3(2*DD*HID/8/256, EE), 256, 0, sW>>>(exp_w1, exp_w2);
    cudaEventRecord(evWX, sW);

    // attention branch (main stream)
    ln_kernel<<<NTOK, 256>>>(x, ln1_g, ln1_b, h1h, nullptr);
    cudaStreamWaitEvent(0, evW, 0);
    qkv_g2<<<dim3(18, 32), 128, SMEMB_G2>>>();
    flash_tc<<<dim3(4, BHN), 256, FLASH_SMEM>>>();
    proj_g2<<<dim3(6, 32), 128, SMEMB_G2>>>(proj_b, x);

    // ln2 -> fork shared-expert chain onto sB
    ln_kernel<<<NTOK, 256>>>(x2, ln2_g, ln2_b, h2h, h2f);
    cudaEventRecord(evF2, 0);
    cudaStreamWaitEvent(sB, evF2, 0);
    shared_hid_g2<<<dim3(24, 32), 128, SMEMB_G2, sB>>>(sh_b1);
    final_split_g2<<<dim3(6, 32, 2), 128, SMEMB_G2, sB>>>();
    cudaEventRecord(evB, sB);

    // routed-expert chain (main stream, overlaps sB)
    seqmean_kernel<<<dim3(3, BB), 256>>>();
    router_kernel<<<BB, 256>>>(router_w1, router_b1, router_w2, router_b2);
    cudaStreamWaitEvent(0, evWX, 0);
    expert_hid_g2<<<dim3(12, 4, BB * KK), 128, SMEMB_G2>>>(exp_b1);
    expert_out_g2<<<dim3(6, 4, BB), 128, SMEMB_G2>>>(exp_b2);

    // join and reduce
    cudaStreamWaitEvent(0, evB, 0);
    final_sum_kernel<<<NTOK * DD / 4 / 256, 256>>>(sh_b2, out);
}

// round 13
// speedup vs baseline: 1.0538x; 1.0538x over previous
#include <cuda_runtime.h>
#include <cuda_fp16.h>
#include <cstdint>
#include <math.h>

// ---------------- problem constants ----------------
#define BB   8
#define SS   512
#define DD   768
#define HH   12
#define DH   64
#define EE   14
#define KK   4
#define HID  1536
#define SHH  3072
#define NTOK (BB*SS)          // 4096
#define BHN  (BB*HH)          // 96

// ---------------- scratch (device globals; no allocation) ----------------
__device__ __align__(128) __half g_h1h [(size_t)NTOK*DD];
__device__ __align__(128) __half g_qh  [(size_t)BHN*SS*DH];
__device__ __align__(128) __half g_kh  [(size_t)BHN*SS*DH];
__device__ __align__(128) __half g_vh  [(size_t)BHN*SS*DH];
__device__ __align__(128) __half g_aoh [(size_t)NTOK*DD];
__device__ __align__(128) float  g_x2  [(size_t)NTOK*DD];
__device__ __align__(128) float  g_h2f [(size_t)NTOK*DD];
__device__ __align__(128) __half g_h2h [(size_t)NTOK*DD];
__device__ __align__(128) float  g_seq [(size_t)BB*DD];
__device__ __align__(128) float  g_wgt [(size_t)BB*EE];
__device__ __align__(128) __half g_ehidh[(size_t)EE*BB*SS*HID];
__device__ __align__(128) __half g_shidh[(size_t)NTOK*SHH];
__device__ __align__(128) float  g_part[6][(size_t)NTOK*DD];   // 0..3 expert slots, 4..5 final
// fp16 weight mirrors, [K][N] row-major
__device__ __align__(128) __half g_qkvw_h [(size_t)DD*3*DD];
__device__ __align__(128) __half g_projw_h[(size_t)DD*DD];
__device__ __align__(128) __half g_shw1_h [(size_t)DD*SHH];
__device__ __align__(128) __half g_shw2_h [(size_t)SHH*DD];
__device__ __align__(128) __half g_expw1_h[(size_t)EE*DD*HID];
__device__ __align__(128) __half g_expw2_h[(size_t)EE*HID*DD];

// ---------------- helpers ----------------
__device__ __forceinline__ float geluf(float x) {
    return 0.5f * x * (1.0f + erff(x * 0.70710678118654752f));
}
__device__ __forceinline__ uint32_t packh2(float a, float b) {
    __half2 h = __floats2half2_rn(a, b);
    return *(uint32_t*)&h;
}
__device__ __forceinline__ void cp16h(__half* dst_smem, const __half* src) {
    uint32_t d = (uint32_t)__cvta_generic_to_shared(dst_smem);
    asm volatile("cp.async.cg.shared.global [%0], [%1], 16;" :: "r"(d), "l"(src));
}
__device__ __forceinline__ void ldsm4(uint32_t &r0, uint32_t &r1, uint32_t &r2, uint32_t &r3,
                                      uint32_t addr) {
    asm volatile("ldmatrix.sync.aligned.m8n8.x4.shared.b16 {%0,%1,%2,%3}, [%4];"
                 : "=r"(r0), "=r"(r1), "=r"(r2), "=r"(r3) : "r"(addr));
}
__device__ __forceinline__ void ldsm4t(uint32_t &r0, uint32_t &r1, uint32_t &r2, uint32_t &r3,
                                       uint32_t addr) {
    asm volatile("ldmatrix.sync.aligned.m8n8.x4.trans.shared.b16 {%0,%1,%2,%3}, [%4];"
                 : "=r"(r0), "=r"(r1), "=r"(r2), "=r"(r3) : "r"(addr));
}
__device__ __forceinline__ void mma_f16(float c[4], const uint32_t a[4], const uint32_t b[2]) {
    asm volatile("mma.sync.aligned.m16n8k16.row.col.f32.f16.f16.f32 "
                 "{%0,%1,%2,%3}, {%4,%5,%6,%7}, {%8,%9}, {%0,%1,%2,%3};"
                 : "+f"(c[0]), "+f"(c[1]), "+f"(c[2]), "+f"(c[3])
                 : "r"(a[0]), "r"(a[1]), "r"(a[2]), "r"(a[3]), "r"(b[0]), "r"(b[1]));
}

__device__ __forceinline__ float blockReduceSum(float v, float* sh) {
    int tid = threadIdx.x;
    sh[tid] = v; __syncthreads();
    for (int s = 128; s > 0; s >>= 1) {
        if (tid < s) sh[tid] += sh[tid + s];
        __syncthreads();
    }
    float r = sh[0]; __syncthreads();
    return r;
}

// ======================================================================
// fp16 GEMM core: 128 threads / 4 warps, warp tile 64x64, CTA 128x128,
// BK=64, 3-stage cp.async, one barrier per 64 k-elements, register
// double-buffered fragments.
// A: [M][K] fp16 row-major (pre-offset), smem [m][k] ld=72.
// B: [K][N] fp16 row-major (pre-offset), smem [k][n] ld=136, ldmatrix.trans.
// ======================================================================
#define G2_LDA 72
#define G2_LDB 136
#define G2_ASZ (128*G2_LDA)
#define G2_BSZ (64*G2_LDB)
#define G2_STG (G2_ASZ + G2_BSZ)          // 17920 halves = 35840 B
#define SMEMB_G2 (3 * G2_STG * 2)         // 107520 B

__device__ __forceinline__ void gemm2(const __half* __restrict__ A, int lda,
                                      const __half* __restrict__ B, int ldb,
                                      int K, __half* smem, float acc[4][8][4])
{
    const int tid  = threadIdx.x;         // 128
    const int lane = tid & 31;
    const int w    = tid >> 5;
    const int wm   = w >> 1;
    const int wn   = w & 1;
    const int l16  = lane & 15;
    const int lh   = lane >> 4;

#define G2_LOAD(kt, stg)                                                     \
    { __half* bA = smem + (stg) * G2_STG;                                    \
      __half* bBp = bA + G2_ASZ;                                             \
      _Pragma("unroll")                                                      \
      for (int i = 0; i < 8; i++) {                                          \
          int e = tid + i * 128; int row = e >> 3, v = e & 7;                \
          cp16h(bA + row * G2_LDA + v * 8, A + (size_t)row * lda + (kt) + v * 8); } \
      _Pragma("unroll")                                                      \
      for (int i = 0; i < 8; i++) {                                          \
          int e = tid + i * 128; int row = e >> 4, v = e & 15;               \
          cp16h(bBp + row * G2_LDB + v * 8, B + (size_t)((kt) + row) * ldb + v * 8); } }

#define G2_FRAG(kk, buf, aB, bBa)                                            \
    { int k0 = (kk) * 16;                                                    \
      _Pragma("unroll")                                                      \
      for (int mt = 0; mt < 4; mt++)                                         \
          ldsm4(a[buf][mt][0], a[buf][mt][1], a[buf][mt][2], a[buf][mt][3],  \
                (aB) + 2u * ((wm * 64 + mt * 16 + l16) * G2_LDA + k0 + lh * 8)); \
      _Pragma("unroll")                                                      \
      for (int p = 0; p < 4; p++) {                                          \
          uint32_t r0, r1, r2, r3;                                           \
          ldsm4t(r0, r1, r2, r3,                                             \
                 (bBa) + 2u * ((k0 + l16) * G2_LDB + wn * 64 + p * 16 + lh * 8)); \
          b[buf][2 * p][0] = r0; b[buf][2 * p][1] = r1;                      \
          b[buf][2 * p + 1][0] = r2; b[buf][2 * p + 1][1] = r3; } }

    const int nst = K / 64;
    G2_LOAD(0, 0);
    asm volatile("cp.async.commit_group;");
    G2_LOAD(64, 1);
    asm volatile("cp.async.commit_group;");

    uint32_t a[2][4][4], b[2][8][2];

    int stg = 0;
    for (int t = 0; t < nst; t++) {
        if (t + 1 < nst) asm volatile("cp.async.wait_group 1;" ::: "memory");
        else             asm volatile("cp.async.wait_group 0;" ::: "memory");
        __syncthreads();
        if (t + 2 < nst) {
            int ns = stg + 2; if (ns >= 3) ns -= 3;
            G2_LOAD((t + 2) * 64, ns);
            asm volatile("cp.async.commit_group;");
        }
        __half* cA = smem + stg * G2_STG;
        uint32_t aB = (uint32_t)__cvta_generic_to_shared(cA);
        uint32_t bBa = (uint32_t)__cvta_generic_to_shared(cA + G2_ASZ);

        G2_FRAG(0, 0, aB, bBa);
#pragma unroll
        for (int kk = 0; kk < 4; kk++) {
            if (kk < 3) G2_FRAG(kk + 1, (kk + 1) & 1, aB, bBa);
#pragma unroll
            for (int mt = 0; mt < 4; mt++)
#pragma unroll
                for (int nt = 0; nt < 8; nt++)
                    mma_f16(acc[mt][nt], a[kk & 1][mt], b[kk & 1][nt]);
        }
        if (++stg == 3) stg = 0;
    }
#undef G2_LOAD
#undef G2_FRAG
}

#define EPI2_SETUP()                                            \
    const int tid = threadIdx.x;                                \
    const int lane = tid & 31, w = tid >> 5;                    \
    const int wm = w >> 1, wn = w & 1;                          \
    const int g = lane >> 2, tig = lane & 3;

// ---------------- gemm2 kernels (128 threads each) ----------------

__global__ void __launch_bounds__(128) qkv_g2()
{
    extern __shared__ __half smem[];
    int row0 = blockIdx.y * 128, col0 = blockIdx.x * 128;
    float acc[4][8][4] = {};
    gemm2(g_h1h + (size_t)row0 * DD, DD, g_qkvw_h + col0, 3 * DD, DD, smem, acc);
    EPI2_SETUP();
#pragma unroll
    for (int mt = 0; mt < 4; mt++)
#pragma unroll
        for (int nt = 0; nt < 8; nt++) {
            int n = col0 + wn * 64 + nt * 8 + 2 * tig;
            int which = n / DD;
            int rem = n - which * DD;
            int h = rem >> 6, d = rem & 63;
            __half* dst = (which == 0) ? g_qh : ((which == 1) ? g_kh : g_vh);
#pragma unroll
            for (int hf = 0; hf < 2; hf++) {
                int m = row0 + wm * 64 + mt * 16 + g + hf * 8;
                int b = m >> 9, s = m & 511;
                *(__half2*)&dst[(((size_t)b * HH + h) * SS + s) * DH + d] =
                    __floats2half2_rn(acc[mt][nt][2 * hf], acc[mt][nt][2 * hf + 1]);
            }
        }
}

__global__ void __launch_bounds__(128) proj_g2(const float* __restrict__ bias,
                                               const float* __restrict__ x)
{
    extern __shared__ __half smem[];
    int row0 = blockIdx.y * 128, col0 = blockIdx.x * 128;
    float acc[4][8][4] = {};
    gemm2(g_aoh + (size_t)row0 * DD, DD, g_projw_h + col0, DD, DD, smem, acc);
    EPI2_SETUP();
#pragma unroll
    for (int mt = 0; mt < 4; mt++)
#pragma unroll
        for (int nt = 0; nt < 8; nt++) {
            int n = col0 + wn * 64 + nt * 8 + 2 * tig;
            float b0 = bias[n], b1 = bias[n + 1];
#pragma unroll
            for (int hf = 0; hf < 2; hf++) {
                int m = row0 + wm * 64 + mt * 16 + g + hf * 8;
                size_t idx = (size_t)m * DD + n;
                float2 xv = *(const float2*)&x[idx];
                *(float2*)&g_x2[idx] =
                    make_float2(xv.x + acc[mt][nt][2 * hf] + b0,
                                xv.y + acc[mt][nt][2 * hf + 1] + b1);
            }
        }
}

// expert hidden, slot-parallel (z = b*KK + slot, 32 slices, all active)
__global__ void __launch_bounds__(128) expert_hid_g2(const float* __restrict__ b1)
{
    extern __shared__ __half smem[];
    int b = blockIdx.z >> 2, slot = blockIdx.z & 3;
    int e = 0; float wv = 0.0f;
    {
        int cnt = -1;
        for (int j = 0; j < EE; j++) {
            float t = g_wgt[b * EE + j];
            if (t != 0.0f) { cnt++; if (cnt == slot) { e = j; wv = t; break; } }
        }
    }
    int row0 = blockIdx.y * 128, col0 = blockIdx.x * 128;
    float acc[4][8][4] = {};
    gemm2(g_h2h + ((size_t)b * SS + row0) * DD, DD,
          g_expw1_h + (size_t)e * DD * HID + col0, HID, DD, smem, acc);
    EPI2_SETUP();
    __half* dst = g_ehidh + ((size_t)e * BB + b) * SS * HID;
#pragma unroll
    for (int mt = 0; mt < 4; mt++)
#pragma unroll
        for (int nt = 0; nt < 8; nt++) {
            int n = col0 + wn * 64 + nt * 8 + 2 * tig;
            float b0 = b1[e * HID + n], bx = b1[e * HID + n + 1];
#pragma unroll
            for (int hf = 0; hf < 2; hf++) {
                int m = row0 + wm * 64 + mt * 16 + g + hf * 8;
                *(__half2*)&dst[(size_t)m * HID + n] =
                    __floats2half2_rn(wv * geluf(acc[mt][nt][2 * hf] + b0),
                                      wv * geluf(acc[mt][nt][2 * hf + 1] + bx));
            }
        }
}

// expert out, slot-parallel: one block set per (b, slot) -> g_part[slot]
__global__ void __launch_bounds__(128) expert_out_g2(const float* __restrict__ b2)
{
    extern __shared__ __half smem[];
    int b = blockIdx.z >> 2, slot = blockIdx.z & 3;
    int e = 0; float wv = 0.0f;
    {
        int cnt = -1;
        for (int j = 0; j < EE; j++) {
            float t = g_wgt[b * EE + j];
            if (t != 0.0f) { cnt++; if (cnt == slot) { e = j; wv = t; break; } }
        }
    }
    int row0 = blockIdx.y * 128, col0 = blockIdx.x * 128;
    float acc[4][8][4] = {};
    gemm2(g_ehidh + (((size_t)e * BB + b) * SS + row0) * HID, HID,
          g_expw2_h + (size_t)e * HID * DD + col0, DD, HID, smem, acc);
    EPI2_SETUP();
    float* dst = g_part[slot];
#pragma unroll
    for (int mt = 0; mt < 4; mt++)
#pragma unroll
        for (int nt = 0; nt < 8; nt++) {
            int n = col0 + wn * 64 + nt * 8 + 2 * tig;
            float b0 = wv * b2[e * DD + n], b1v = wv * b2[e * DD + n + 1];
#pragma unroll
            for (int hf = 0; hf < 2; hf++) {
                int m = row0 + wm * 64 + mt * 16 + g + hf * 8;
                *(float2*)&dst[((size_t)b * SS + m) * DD + n] =
                    make_float2(acc[mt][nt][2 * hf] + b0,
                                acc[mt][nt][2 * hf + 1] + b1v);
            }
        }
}

__global__ void __launch_bounds__(128) shared_hid_g2(const float* __restrict__ b1)
{
    extern __shared__ __half smem[];
    int row0 = blockIdx.y * 128, col0 = blockIdx.x * 128;
    float acc[4][8][4] = {};
    gemm2(g_h2h + (size_t)row0 * DD, DD, g_shw1_h + col0, SHH, DD, smem, acc);
    EPI2_SETUP();
#pragma unroll
    for (int mt = 0; mt < 4; mt++)
#pragma unroll
        for (int nt = 0; nt < 8; nt++) {
            int n = col0 + wn * 64 + nt * 8 + 2 * tig;
            float b0 = b1[n], bx = b1[n + 1];
#pragma unroll
            for (int hf = 0; hf < 2; hf++) {
                int m = row0 + wm * 64 + mt * 16 + g + hf * 8;
                *(__half2*)&g_shidh[(size_t)m * SHH + n] =
                    __floats2half2_rn(geluf(acc[mt][nt][2 * hf] + b0),
                                      geluf(acc[mt][nt][2 * hf + 1] + bx));
            }
        }
}

// final split-K chunk c (2 chunks of K=1536): g_part[4+c]
__global__ void __launch_bounds__(128) final_split_g2()
{
    extern __shared__ __half smem[];
    int c = blockIdx.z;
    int row0 = blockIdx.y * 128, col0 = blockIdx.x * 128;
    float acc[4][8][4] = {};
    gemm2(g_shidh + (size_t)row0 * SHH + c * 1536, SHH,
          g_shw2_h + (size_t)(c * 1536) * DD + col0, DD, 1536, smem, acc);
    EPI2_SETUP();
    float* dst = g_part[4 + c];
#pragma unroll
    for (int mt = 0; mt < 4; mt++)
#pragma unroll
        for (int nt = 0; nt < 8; nt++) {
            int n = col0 + wn * 64 + nt * 8 + 2 * tig;
#pragma unroll
            for (int hf = 0; hf < 2; hf++) {
                int m = row0 + wm * 64 + mt * 16 + g + hf * 8;
                *(float2*)&dst[(size_t)m * DD + n] =
                    make_float2(acc[mt][nt][2 * hf], acc[mt][nt][2 * hf + 1]);
            }
        }
}

// ---------------- flash attention (fp16, P in registers) ----------------
#define FLDA 72
#define FLASH_SMEM (3 * 128 * FLDA * 2)

__global__ void __launch_bounds__(256, 1) flash_tc()
{
    extern __shared__ __half hsm[];
    __half* sQ = hsm;
    __half* sK = hsm + 128 * FLDA;
    __half* sV = hsm + 2 * 128 * FLDA;

    const int bh = blockIdx.y;
    const int q0 = blockIdx.x * 128;
    const __half* Qg = g_qh + ((size_t)bh * SS + q0) * DH;
    const __half* Kg = g_kh + (size_t)bh * SS * DH;
    const __half* Vg = g_vh + (size_t)bh * SS * DH;

    const int tid = threadIdx.x, lane = tid & 31, w = tid >> 5;
    const int l16 = lane & 15, lh = lane >> 4;
    const int g = lane >> 2, tig = lane & 3;

#define FCOPY(dst, src)                                                       \
    { _Pragma("unroll")                                                       \
      for (int i = 0; i < 4; i++) {                                           \
          int e = tid + i * 256; int r = e >> 3, v = e & 7;                   \
          cp16h((dst) + r * FLDA + v * 8, (src) + (size_t)r * 64 + v * 8); } }

    FCOPY(sQ, Qg);
    FCOPY(sK, Kg);
    asm volatile("cp.async.commit_group;");
    FCOPY(sV, Vg);
    asm volatile("cp.async.commit_group;");

    float acc_o[8][4] = {};
    float mrun[2] = {-1e30f, -1e30f};
    float lrun[2] = {0.0f, 0.0f};

    const uint32_t sQa = (uint32_t)__cvta_generic_to_shared(sQ);
    const uint32_t sKa = (uint32_t)__cvta_generic_to_shared(sK);
    const uint32_t sVa = (uint32_t)__cvta_generic_to_shared(sV);

    for (int st = 0; st < 4; st++) {
        asm volatile("cp.async.wait_group 1;" ::: "memory");
        __syncthreads();

        float s[16][4] = {};
#pragma unroll
        for (int kk = 0; kk < 4; kk++) {
            int k0 = kk * 16;
            uint32_t a[4];
            ldsm4(a[0], a[1], a[2], a[3],
                  sQa + 2u * ((w * 16 + l16) * FLDA + k0 + lh * 8));
#pragma unroll
            for (int p = 0; p < 8; p++) {
                uint32_t r0, r1, r2, r3;
                ldsm4(r0, r1, r2, r3,
                      sKa + 2u * ((p * 16 + l16) * FLDA + k0 + lh * 8));
                uint32_t b0[2] = {r0, r2}, b1[2] = {r1, r3};
                mma_f16(s[2 * p], a, b0);
                mma_f16(s[2 * p + 1], a, b1);
            }
        }

        float tmax[2] = {-1e30f, -1e30f};
#pragma unroll
        for (int nt = 0; nt < 16; nt++) {
            tmax[0] = fmaxf(tmax[0], fmaxf(s[nt][0], s[nt][1]));
            tmax[1] = fmaxf(tmax[1], fmaxf(s[nt][2], s[nt][3]));
        }
#pragma unroll
        for (int o = 1; o < 4; o <<= 1) {
            tmax[0] = fmaxf(tmax[0], __shfl_xor_sync(0xffffffffu, tmax[0], o));
            tmax[1] = fmaxf(tmax[1], __shfl_xor_sync(0xffffffffu, tmax[1], o));
        }
        float mnew[2], corr[2], rsum[2] = {0.0f, 0.0f};
#pragma unroll
        for (int h = 0; h < 2; h++) {
            mnew[h] = fmaxf(mrun[h], tmax[h] * 0.125f);
            corr[h] = __expf(mrun[h] - mnew[h]);
            mrun[h] = mnew[h];
        }
        uint32_t ph[16][2];
#pragma unroll
        for (int nt = 0; nt < 16; nt++) {
            float p0 = __expf(s[nt][0] * 0.125f - mnew[0]);
            float p1 = __expf(s[nt][1] * 0.125f - mnew[0]);
            float p2 = __expf(s[nt][2] * 0.125f - mnew[1]);
            float p3 = __expf(s[nt][3] * 0.125f - mnew[1]);
            rsum[0] += p0 + p1; rsum[1] += p2 + p3;
            ph[nt][0] = packh2(p0, p1);
            ph[nt][1] = packh2(p2, p3);
        }
#pragma unroll
        for (int o = 1; o < 4; o <<= 1) {
            rsum[0] += __shfl_xor_sync(0xffffffffu, rsum[0], o);
            rsum[1] += __shfl_xor_sync(0xffffffffu, rsum[1], o);
        }
        lrun[0] = lrun[0] * corr[0] + rsum[0];
        lrun[1] = lrun[1] * corr[1] + rsum[1];
#pragma unroll
        for (int nt = 0; nt < 8; nt++) {
            acc_o[nt][0] *= corr[0]; acc_o[nt][1] *= corr[0];
            acc_o[nt][2] *= corr[1]; acc_o[nt][3] *= corr[1];
        }

        asm volatile("cp.async.wait_group 0;" ::: "memory");
        __syncthreads();
        if (st < 3) {
            FCOPY(sK, Kg + (size_t)(st + 1) * 128 * 64);
            asm volatile("cp.async.commit_group;");
        }

#pragma unroll
        for (int j = 0; j < 8; j++) {
            int k0 = j * 16;
            uint32_t a[4] = {ph[2 * j][0], ph[2 * j][1], ph[2 * j + 1][0], ph[2 * j + 1][1]};
#pragma unroll
            for (int p = 0; p < 4; p++) {
                uint32_t r0, r1, r2, r3;
                ldsm4t(r0, r1, r2, r3,
                       sVa + 2u * ((k0 + l16) * FLDA + p * 16 + lh * 8));
                uint32_t b0[2] = {r0, r1}, b1[2] = {r2, r3};
                mma_f16(acc_o[2 * p], a, b0);
                mma_f16(acc_o[2 * p + 1], a, b1);
            }
        }
        __syncthreads();
        if (st < 3) {
            FCOPY(sV, Vg + (size_t)(st + 1) * 128 * 64);
            asm volatile("cp.async.commit_group;");
        }
    }

    const int b = bh / HH, hh = bh - b * HH;
    const float inv0 = 1.0f / lrun[0], inv1 = 1.0f / lrun[1];
    const int m0 = q0 + w * 16 + g;
#pragma unroll
    for (int nt = 0; nt < 8; nt++) {
        int d = nt * 8 + 2 * tig;
        *(__half2*)&g_aoh[((size_t)b * SS + m0) * DD + hh * DH + d] =
            __floats2half2_rn(acc_o[nt][0] * inv0, acc_o[nt][1] * inv0);
        *(__half2*)&g_aoh[((size_t)b * SS + m0 + 8) * DD + hh * DH + d] =
            __floats2half2_rn(acc_o[nt][2] * inv1, acc_o[nt][3] * inv1);
    }
#undef FCOPY
}

// ---------------- conversion kernels ----------------
__global__ void f2h_kernel(const float* __restrict__ in, __half* __restrict__ out, int n8)
{
    int i = blockIdx.x * 256 + threadIdx.x;
    if (i >= n8) return;
    float4 a = ((const float4*)in)[2 * i];
    float4 b = ((const float4*)in)[2 * i + 1];
    uint4 u;
    u.x = packh2(a.x, a.y); u.y = packh2(a.z, a.w);
    u.z = packh2(b.x, b.y); u.w = packh2(b.z, b.w);
    ((uint4*)out)[i] = u;
}

__global__ void expconv_kernel(const float* __restrict__ w1, const float* __restrict__ w2)
{
    int e = blockIdx.y;
    int i = blockIdx.x * 256 + threadIdx.x;
    const int n8 = DD * HID / 8;
    const float* src; __half* dst; int j;
    if (i < n8) { src = w1 + (size_t)e * DD * HID; dst = g_expw1_h + (size_t)e * DD * HID; j = i; }
    else        { src = w2 + (size_t)e * HID * DD; dst = g_expw2_h + (size_t)e * HID * DD; j = i - n8; }
    float4 a = ((const float4*)src)[2 * j];
    float4 b = ((const float4*)src)[2 * j + 1];
    uint4 u;
    u.x = packh2(a.x, a.y); u.y = packh2(a.z, a.w);
    u.z = packh2(b.x, b.y); u.w = packh2(b.z, b.w);
    ((uint4*)dst)[j] = u;
}

// ---------------- elementwise kernels ----------------
__global__ void ln_kernel(const float* __restrict__ in, const float* __restrict__ g,
                          const float* __restrict__ b, __half* __restrict__ outh,
                          float* __restrict__ outf)
{
    __shared__ float red[256];
    size_t row = blockIdx.x;
    const float* xr = in + row * DD;
    int tid = threadIdx.x;
    float x0 = xr[tid], x1 = xr[tid + 256], x2 = xr[tid + 512];
    float total = blockReduceSum(x0 + x1 + x2, red);
    float mean = total * (1.0f / DD);
    float d0 = x0 - mean, d1 = x1 - mean, d2 = x2 - mean;
    float var = blockReduceSum(d0 * d0 + d1 * d1 + d2 * d2, red) * (1.0f / DD);
    float rstd = rsqrtf(var + 1e-5f);
    float r0 = d0 * rstd * g[tid]       + b[tid];
    float r1 = d1 * rstd * g[tid + 256] + b[tid + 256];
    float r2 = d2 * rstd * g[tid + 512] + b[tid + 512];
    outh[row * DD + tid]       = __float2half_rn(r0);
    outh[row * DD + tid + 256] = __float2half_rn(r1);
    outh[row * DD + tid + 512] = __float2half_rn(r2);
    if (outf) {
        outf[row * DD + tid]       = r0;
        outf[row * DD + tid + 256] = r1;
        outf[row * DD + tid + 512] = r2;
    }
}

__global__ void seqmean_kernel()
{
    int b = blockIdx.y;
    int d = blockIdx.x * 256 + threadIdx.x;
    const float* p = g_h2f + (size_t)b * SS * DD + d;
    float s = 0.0f;
    for (int i = 0; i < SS; i++) s += p[(size_t)i * DD];
    g_seq[b * DD + d] = s * (1.0f / SS);
}

__global__ void router_kernel(const float* __restrict__ w1, const float* __restrict__ b1,
                              const float* __restrict__ w2, const float* __restrict__ b2)
{
    __shared__ float s_in[DD];
    __shared__ float s_hid[DD];
    __shared__ float s_logits[EE];
    int b = blockIdx.x;
    int tid = threadIdx.x;
    for (int i = tid; i < DD; i += 256) s_in[i] = g_seq[b * DD + i];
    __syncthreads();
    for (int j = tid; j < DD; j += 256) {
        float a = b1[j];
        for (int d = 0; d < DD; d++) a = fmaf(s_in[d], w1[(size_t)d * DD + j], a);
        s_hid[j] = geluf(a);
    }
    __syncthreads();
    if (tid < EE) {
        float a = b2[tid];
        for (int d = 0; d < DD; d++) a = fmaf(s_hid[d], w2[(size_t)d * EE + tid], a);
        s_logits[tid] = a;
    }
    __syncthreads();
    if (tid == 0) {
        float p[EE];
        float mx = -1e30f;
        for (int e = 0; e < EE; e++) mx = fmaxf(mx, s_logits[e]);
        float sum = 0.0f;
        for (int e = 0; e < EE; e++) { p[e] = expf(s_logits[e] - mx); sum += p[e]; }
        float inv = 1.0f / sum;
        for (int e = 0; e < EE; e++) p[e] *= inv;
        int   idx[KK];
        float val[KK];
        bool used[EE] = {};
        for (int k = 0; k < KK; k++) {
            int best = -1; float bv = -1e30f;
            for (int e = 0; e < EE; e++)
                if (!used[e] && p[e] > bv) { bv = p[e]; best = e; }
            used[best] = true; idx[k] = best; val[k] = bv;
        }
        float m2 = val[0];
        float s2 = 0.0f, tw[KK];
        for (int k = 0; k < KK; k++) { tw[k] = expf(val[k] - m2); s2 += tw[k]; }
        float inv2 = 1.0f / s2;
        for (int e = 0; e < EE; e++) g_wgt[b * EE + e] = 0.0f;
        for (int k = 0; k < KK; k++) g_wgt[b * EE + idx[k]] = tw[k] * inv2;
    }
}

__global__ void final_sum_kernel(const float* __restrict__ b2, float* __restrict__ out)
{
    int i = blockIdx.x * 256 + threadIdx.x;
    int n = (i % (DD / 4)) * 4;
    float4 r = *(const float4*)(g_x2 + (size_t)i * 4);
#pragma unroll
    for (int j = 0; j < 6; j++) {
        float4 p = *(const float4*)(g_part[j] + (size_t)i * 4);
        r.x += p.x; r.y += p.y; r.z += p.z; r.w += p.w;
    }
    float4 bb = *(const float4*)(b2 + n);
    r.x += bb.x; r.y += bb.y; r.z += bb.z; r.w += bb.w;
    *(float4*)(out + (size_t)i * 4) = r;
}

// ---------------- launch ----------------
extern "C" void kernel_launch(void* const* d_in, const int* in_sizes, int n_in,
                              void* d_out, int out_size)
{
    const float* x         = (const float*)d_in[0];
    const float* ln1_g     = (const float*)d_in[1];
    const float* ln1_b     = (const float*)d_in[2];
    const float* qkv_w     = (const float*)d_in[3];
    const float* proj_w    = (const float*)d_in[4];
    const float* proj_b    = (const float*)d_in[5];
    const float* ln2_g     = (const float*)d_in[6];
    const float* ln2_b     = (const float*)d_in[7];
    const float* router_w1 = (const float*)d_in[8];
    const float* router_b1 = (const float*)d_in[9];
    const float* router_w2 = (const float*)d_in[10];
    const float* router_b2 = (const float*)d_in[11];
    const float* exp_w1    = (const float*)d_in[12];
    const float* exp_b1    = (const float*)d_in[13];
    const float* exp_w2    = (const float*)d_in[14];
    const float* exp_b2    = (const float*)d_in[15];
    const float* sh_w1     = (const float*)d_in[16];
    const float* sh_b1     = (const float*)d_in[17];
    const float* sh_w2     = (const float*)d_in[18];
    const float* sh_b2     = (const float*)d_in[19];
    float* out = (float*)d_out;

    static cudaStream_t sW = nullptr, sB = nullptr;
    static cudaEvent_t evF1 = nullptr, evW = nullptr, evWX = nullptr,
                       evF2 = nullptr, evB = nullptr;
    if (!sW) {
        cudaStreamCreateWithFlags(&sW, cudaStreamNonBlocking);
        cudaStreamCreateWithFlags(&sB, cudaStreamNonBlocking);
        cudaEventCreateWithFlags(&evF1, cudaEventDisableTiming);
        cudaEventCreateWithFlags(&evW,  cudaEventDisableTiming);
        cudaEventCreateWithFlags(&evWX, cudaEventDisableTiming);
        cudaEventCreateWithFlags(&evF2, cudaEventDisableTiming);
        cudaEventCreateWithFlags(&evB,  cudaEventDisableTiming);
    }

    cudaFuncSetAttribute(qkv_g2,        cudaFuncAttributeMaxDynamicSharedMemorySize, SMEMB_G2);
    cudaFuncSetAttribute(proj_g2,       cudaFuncAttributeMaxDynamicSharedMemorySize, SMEMB_G2);
    cudaFuncSetAttribute(expert_hid_g2, cudaFuncAttributeMaxDynamicSharedMemorySize, SMEMB_G2);
    cudaFuncSetAttribute(expert_out_g2, cudaFuncAttributeMaxDynamicSharedMemorySize, SMEMB_G2);
    cudaFuncSetAttribute(shared_hid_g2, cudaFuncAttributeMaxDynamicSharedMemorySize, SMEMB_G2);
    cudaFuncSetAttribute(final_split_g2,cudaFuncAttributeMaxDynamicSharedMemorySize, SMEMB_G2);
    cudaFuncSetAttribute(flash_tc,      cudaFuncAttributeMaxDynamicSharedMemorySize, FLASH_SMEM);

    __half* wq;  cudaGetSymbolAddress((void**)&wq,  g_qkvw_h);
    __half* wp;  cudaGetSymbolAddress((void**)&wp,  g_projw_h);
    __half* w1;  cudaGetSymbolAddress((void**)&w1,  g_shw1_h);
    __half* w2;  cudaGetSymbolAddress((void**)&w2,  g_shw2_h);
    __half* h1h; cudaGetSymbolAddress((void**)&h1h, g_h1h);
    __half* h2h; cudaGetSymbolAddress((void**)&h2h, g_h2h);
    float*  h2f; cudaGetSymbolAddress((void**)&h2f, g_h2f);
    float*  x2;  cudaGetSymbolAddress((void**)&x2,  g_x2);

    // fork sW: weight conversions (attn/shared first, then all experts)
    cudaEventRecord(evF1, 0);
    cudaStreamWaitEvent(sW, evF1, 0);
    f2h_kernel<<<(DD*3*DD/8 + 255)/256, 256, 0, sW>>>(qkv_w, wq, DD*3*DD/8);
    f2h_kernel<<<(DD*DD/8   + 255)/256, 256, 0, sW>>>(proj_w, wp, DD*DD/8);
    f2h_kernel<<<(DD*SHH/8  + 255)/256, 256, 0, sW>>>(sh_w1, w1, DD*SHH/8);
    f2h_kernel<<<(SHH*DD/8  + 255)/256, 256, 0, sW>>>(sh_w2, w2, SHH*DD/8);
    cudaEventRecord(evW, sW);
    expconv_kernel<<<dim3(2*DD*HID/8/256, EE), 256, 0, sW>>>(exp_w1, exp_w2);
    cudaEventRecord(evWX, sW);

    // attention branch (main stream)
    ln_kernel<<<NTOK, 256>>>(x, ln1_g, ln1_b, h1h, nullptr);
    cudaStreamWaitEvent(0, evW, 0);
    qkv_g2<<<dim3(18, 32), 128, SMEMB_G2>>>();
    flash_tc<<<dim3(4, BHN), 256, FLASH_SMEM>>>();
    proj_g2<<<dim3(6, 32), 128, SMEMB_G2>>>(proj_b, x);

    // ln2 -> fork shared-expert chain onto sB
    ln_kernel<<<NTOK, 256>>>(x2, ln2_g, ln2_b, h2h, h2f);
    cudaEventRecord(evF2, 0);
    cudaStreamWaitEvent(sB, evF2, 0);
    shared_hid_g2<<<dim3(24, 32), 128, SMEMB_G2, sB>>>(sh_b1);
    final_split_g2<<<dim3(6, 32, 2), 128, SMEMB_G2, sB>>>();
    cudaEventRecord(evB, sB);

    // routed-expert chain (main stream, overlaps sB)
    seqmean_kernel<<<dim3(3, BB), 256>>>();
    router_kernel<<<BB, 256>>>(router_w1, router_b1, router_w2, router_b2);
    cudaStreamWaitEvent(0, evWX, 0);
    expert_hid_g2<<<dim3(12, 4, BB * KK), 128, SMEMB_G2>>>(exp_b1);
    expert_out_g2<<<dim3(6, 4, BB * KK), 128, SMEMB_G2>>>(exp_b2);

    // join and reduce
    cudaStreamWaitEvent(0, evB, 0);
    final_sum_kernel<<<NTOK * DD / 4 / 256, 256>>>(sh_b2, out);
}

// round 14
// speedup vs baseline: 1.0837x; 1.0284x over previous
#include <cuda_runtime.h>
#include <cuda_fp16.h>
#include <cstdint>
#include <math.h>

// ---------------- problem constants ----------------
#define BB   8
#define SS   512
#define DD   768
#define HH   12
#define DH   64
#define EE   14
#define KK   4
#define HID  1536
#define SHH  3072
#define NTOK (BB*SS)          // 4096
#define BHN  (BB*HH)          // 96

// ---------------- scratch (device globals; no allocation) ----------------
__device__ __align__(128) __half g_h1h [(size_t)NTOK*DD];
__device__ __align__(128) __half g_qh  [(size_t)BHN*SS*DH];
__device__ __align__(128) __half g_kh  [(size_t)BHN*SS*DH];
__device__ __align__(128) __half g_vh  [(size_t)BHN*SS*DH];
__device__ __align__(128) __half g_aoh [(size_t)NTOK*DD];
__device__ __align__(128) float  g_x2  [(size_t)NTOK*DD];
__device__ __align__(128) __half g_h2h [(size_t)NTOK*DD];
__device__ __align__(128) float  g_seq [(size_t)BB*DD];
__device__ __align__(128) float  g_wgt [(size_t)BB*EE];
__device__ __align__(128) __half g_ehidh[(size_t)EE*BB*SS*HID];
__device__ __align__(128) __half g_shidh[(size_t)NTOK*SHH];
__device__ __align__(128) float  g_part[6][(size_t)NTOK*DD];   // 0..3 expert slots, 4..5 final
// fp16 weight mirrors, [K][N] row-major
__device__ __align__(128) __half g_qkvw_h [(size_t)DD*3*DD];
__device__ __align__(128) __half g_projw_h[(size_t)DD*DD];
__device__ __align__(128) __half g_shw1_h [(size_t)DD*SHH];
__device__ __align__(128) __half g_shw2_h [(size_t)SHH*DD];
__device__ __align__(128) __half g_expw1_h[(size_t)EE*DD*HID];
__device__ __align__(128) __half g_expw2_h[(size_t)EE*HID*DD];

// ---------------- helpers ----------------
__device__ __forceinline__ float geluf(float x) {
    return 0.5f * x * (1.0f + erff(x * 0.70710678118654752f));
}
__device__ __forceinline__ uint32_t packh2(float a, float b) {
    __half2 h = __floats2half2_rn(a, b);
    return *(uint32_t*)&h;
}
__device__ __forceinline__ void cp16h(__half* dst_smem, const __half* src) {
    uint32_t d = (uint32_t)__cvta_generic_to_shared(dst_smem);
    asm volatile("cp.async.cg.shared.global [%0], [%1], 16;" :: "r"(d), "l"(src));
}
__device__ __forceinline__ void ldsm4(uint32_t &r0, uint32_t &r1, uint32_t &r2, uint32_t &r3,
                                      uint32_t addr) {
    asm volatile("ldmatrix.sync.aligned.m8n8.x4.shared.b16 {%0,%1,%2,%3}, [%4];"
                 : "=r"(r0), "=r"(r1), "=r"(r2), "=r"(r3) : "r"(addr));
}
__device__ __forceinline__ void ldsm4t(uint32_t &r0, uint32_t &r1, uint32_t &r2, uint32_t &r3,
                                       uint32_t addr) {
    asm volatile("ldmatrix.sync.aligned.m8n8.x4.trans.shared.b16 {%0,%1,%2,%3}, [%4];"
                 : "=r"(r0), "=r"(r1), "=r"(r2), "=r"(r3) : "r"(addr));
}
__device__ __forceinline__ void mma_f16(float c[4], const uint32_t a[4], const uint32_t b[2]) {
    asm volatile("mma.sync.aligned.m16n8k16.row.col.f32.f16.f16.f32 "
                 "{%0,%1,%2,%3}, {%4,%5,%6,%7}, {%8,%9}, {%0,%1,%2,%3};"
                 : "+f"(c[0]), "+f"(c[1]), "+f"(c[2]), "+f"(c[3])
                 : "r"(a[0]), "r"(a[1]), "r"(a[2]), "r"(a[3]), "r"(b[0]), "r"(b[1]));
}

__device__ __forceinline__ float blockReduceSum(float v, float* sh) {
    int tid = threadIdx.x;
    sh[tid] = v; __syncthreads();
    for (int s = 128; s > 0; s >>= 1) {
        if (tid < s) sh[tid] += sh[tid + s];
        __syncthreads();
    }
    float r = sh[0]; __syncthreads();
    return r;
}

// ======================================================================
// fp16 GEMM core: 128 threads / 4 warps, warp tile 64x64, CTA 128x128,
// BK=64, 3-stage cp.async, one barrier per 64 k-elements, register
// double-buffered fragments.
// ======================================================================
#define G2_LDA 72
#define G2_LDB 136
#define G2_ASZ (128*G2_LDA)
#define G2_BSZ (64*G2_LDB)
#define G2_STG (G2_ASZ + G2_BSZ)          // 17920 halves = 35840 B
#define SMEMB_G2 (3 * G2_STG * 2)         // 107520 B

__device__ __forceinline__ void gemm2(const __half* __restrict__ A, int lda,
                                      const __half* __restrict__ B, int ldb,
                                      int K, __half* smem, float acc[4][8][4])
{
    const int tid  = threadIdx.x;         // 128
    const int lane = tid & 31;
    const int w    = tid >> 5;
    const int wm   = w >> 1;
    const int wn   = w & 1;
    const int l16  = lane & 15;
    const int lh   = lane >> 4;

#define G2_LOAD(kt, stg)                                                     \
    { __half* bA = smem + (stg) * G2_STG;                                    \
      __half* bBp = bA + G2_ASZ;                                             \
      _Pragma("unroll")                                                      \
      for (int i = 0; i < 8; i++) {                                          \
          int e = tid + i * 128; int row = e >> 3, v = e & 7;                \
          cp16h(bA + row * G2_LDA + v * 8, A + (size_t)row * lda + (kt) + v * 8); } \
      _Pragma("unroll")                                                      \
      for (int i = 0; i < 8; i++) {                                          \
          int e = tid + i * 128; int row = e >> 4, v = e & 15;               \
          cp16h(bBp + row * G2_LDB + v * 8, B + (size_t)((kt) + row) * ldb + v * 8); } }

#define G2_FRAG(kk, buf, aB, bBa)                                            \
    { int k0 = (kk) * 16;                                                    \
      _Pragma("unroll")                                                      \
      for (int mt = 0; mt < 4; mt++)                                         \
          ldsm4(a[buf][mt][0], a[buf][mt][1], a[buf][mt][2], a[buf][mt][3],  \
                (aB) + 2u * ((wm * 64 + mt * 16 + l16) * G2_LDA + k0 + lh * 8)); \
      _Pragma("unroll")                                                      \
      for (int p = 0; p < 4; p++) {                                          \
          uint32_t r0, r1, r2, r3;                                           \
          ldsm4t(r0, r1, r2, r3,                                             \
                 (bBa) + 2u * ((k0 + l16) * G2_LDB + wn * 64 + p * 16 + lh * 8)); \
          b[buf][2 * p][0] = r0; b[buf][2 * p][1] = r1;                      \
          b[buf][2 * p + 1][0] = r2; b[buf][2 * p + 1][1] = r3; } }

    const int nst = K / 64;
    G2_LOAD(0, 0);
    asm volatile("cp.async.commit_group;");
    G2_LOAD(64, 1);
    asm volatile("cp.async.commit_group;");

    uint32_t a[2][4][4], b[2][8][2];

    int stg = 0;
    for (int t = 0; t < nst; t++) {
        if (t + 1 < nst) asm volatile("cp.async.wait_group 1;" ::: "memory");
        else             asm volatile("cp.async.wait_group 0;" ::: "memory");
        __syncthreads();
        if (t + 2 < nst) {
            int ns = stg + 2; if (ns >= 3) ns -= 3;
            G2_LOAD((t + 2) * 64, ns);
            asm volatile("cp.async.commit_group;");
        }
        __half* cA = smem + stg * G2_STG;
        uint32_t aB = (uint32_t)__cvta_generic_to_shared(cA);
        uint32_t bBa = (uint32_t)__cvta_generic_to_shared(cA + G2_ASZ);

        G2_FRAG(0, 0, aB, bBa);
#pragma unroll
        for (int kk = 0; kk < 4; kk++) {
            if (kk < 3) G2_FRAG(kk + 1, (kk + 1) & 1, aB, bBa);
#pragma unroll
            for (int mt = 0; mt < 4; mt++)
#pragma unroll
                for (int nt = 0; nt < 8; nt++)
                    mma_f16(acc[mt][nt], a[kk & 1][mt], b[kk & 1][nt]);
        }
        if (++stg == 3) stg = 0;
    }
#undef G2_LOAD
#undef G2_FRAG
}

#define EPI2_SETUP()                                            \
    const int tid = threadIdx.x;                                \
    const int lane = tid & 31, w = tid >> 5;                    \
    const int wm = w >> 1, wn = w & 1;                          \
    const int g = lane >> 2, tig = lane & 3;

// ---------------- gemm2 kernels (128 threads each) ----------------

__global__ void __launch_bounds__(128) qkv_g2()
{
    extern __shared__ __half smem[];
    int row0 = blockIdx.y * 128, col0 = blockIdx.x * 128;
    float acc[4][8][4] = {};
    gemm2(g_h1h + (size_t)row0 * DD, DD, g_qkvw_h + col0, 3 * DD, DD, smem, acc);
    EPI2_SETUP();
#pragma unroll
    for (int mt = 0; mt < 4; mt++)
#pragma unroll
        for (int nt = 0; nt < 8; nt++) {
            int n = col0 + wn * 64 + nt * 8 + 2 * tig;
            int which = n / DD;
            int rem = n - which * DD;
            int h = rem >> 6, d = rem & 63;
            __half* dst = (which == 0) ? g_qh : ((which == 1) ? g_kh : g_vh);
#pragma unroll
            for (int hf = 0; hf < 2; hf++) {
                int m = row0 + wm * 64 + mt * 16 + g + hf * 8;
                int b = m >> 9, s = m & 511;
                *(__half2*)&dst[(((size_t)b * HH + h) * SS + s) * DH + d] =
                    __floats2half2_rn(acc[mt][nt][2 * hf], acc[mt][nt][2 * hf + 1]);
            }
        }
}

__global__ void __launch_bounds__(128) proj_g2(const float* __restrict__ bias,
                                               const float* __restrict__ x)
{
    extern __shared__ __half smem[];
    int row0 = blockIdx.y * 128, col0 = blockIdx.x * 128;
    float acc[4][8][4] = {};
    gemm2(g_aoh + (size_t)row0 * DD, DD, g_projw_h + col0, DD, DD, smem, acc);
    EPI2_SETUP();
#pragma unroll
    for (int mt = 0; mt < 4; mt++)
#pragma unroll
        for (int nt = 0; nt < 8; nt++) {
            int n = col0 + wn * 64 + nt * 8 + 2 * tig;
            float b0 = bias[n], b1 = bias[n + 1];
#pragma unroll
            for (int hf = 0; hf < 2; hf++) {
                int m = row0 + wm * 64 + mt * 16 + g + hf * 8;
                size_t idx = (size_t)m * DD + n;
                float2 xv = *(const float2*)&x[idx];
                *(float2*)&g_x2[idx] =
                    make_float2(xv.x + acc[mt][nt][2 * hf] + b0,
                                xv.y + acc[mt][nt][2 * hf + 1] + b1);
            }
        }
}

// expert hidden, slot-parallel (z = b*KK + slot, 32 slices, all active)
__global__ void __launch_bounds__(128) expert_hid_g2(const float* __restrict__ b1)
{
    extern __shared__ __half smem[];
    int b = blockIdx.z >> 2, slot = blockIdx.z & 3;
    int e = 0; float wv = 0.0f;
    {
        int cnt = -1;
        for (int j = 0; j < EE; j++) {
            float t = g_wgt[b * EE + j];
            if (t != 0.0f) { cnt++; if (cnt == slot) { e = j; wv = t; break; } }
        }
    }
    int row0 = blockIdx.y * 128, col0 = blockIdx.x * 128;
    float acc[4][8][4] = {};
    gemm2(g_h2h + ((size_t)b * SS + row0) * DD, DD,
          g_expw1_h + (size_t)e * DD * HID + col0, HID, DD, smem, acc);
    EPI2_SETUP();
    __half* dst = g_ehidh + ((size_t)e * BB + b) * SS * HID;
#pragma unroll
    for (int mt = 0; mt < 4; mt++)
#pragma unroll
        for (int nt = 0; nt < 8; nt++) {
            int n = col0 + wn * 64 + nt * 8 + 2 * tig;
            float b0 = b1[e * HID + n], bx = b1[e * HID + n + 1];
#pragma unroll
            for (int hf = 0; hf < 2; hf++) {
                int m = row0 + wm * 64 + mt * 16 + g + hf * 8;
                *(__half2*)&dst[(size_t)m * HID + n] =
                    __floats2half2_rn(wv * geluf(acc[mt][nt][2 * hf] + b0),
                                      wv * geluf(acc[mt][nt][2 * hf + 1] + bx));
            }
        }
}

// expert out, slot-parallel: one block set per (b, slot) -> g_part[slot]
__global__ void __launch_bounds__(128) expert_out_g2(const float* __restrict__ b2)
{
    extern __shared__ __half smem[];
    int b = blockIdx.z >> 2, slot = blockIdx.z & 3;
    int e = 0; float wv = 0.0f;
    {
        int cnt = -1;
        for (int j = 0; j < EE; j++) {
            float t = g_wgt[b * EE + j];
            if (t != 0.0f) { cnt++; if (cnt == slot) { e = j; wv = t; break; } }
        }
    }
    int row0 = blockIdx.y * 128, col0 = blockIdx.x * 128;
    float acc[4][8][4] = {};
    gemm2(g_ehidh + (((size_t)e * BB + b) * SS + row0) * HID, HID,
          g_expw2_h + (size_t)e * HID * DD + col0, DD, HID, smem, acc);
    EPI2_SETUP();
    float* dst = g_part[slot];
#pragma unroll
    for (int mt = 0; mt < 4; mt++)
#pragma unroll
        for (int nt = 0; nt < 8; nt++) {
            int n = col0 + wn * 64 + nt * 8 + 2 * tig;
            float b0 = wv * b2[e * DD + n], b1v = wv * b2[e * DD + n + 1];
#pragma unroll
            for (int hf = 0; hf < 2; hf++) {
                int m = row0 + wm * 64 + mt * 16 + g + hf * 8;
                *(float2*)&dst[((size_t)b * SS + m) * DD + n] =
                    make_float2(acc[mt][nt][2 * hf] + b0,
                                acc[mt][nt][2 * hf + 1] + b1v);
            }
        }
}

__global__ void __launch_bounds__(128) shared_hid_g2(const float* __restrict__ b1)
{
    extern __shared__ __half smem[];
    int row0 = blockIdx.y * 128, col0 = blockIdx.x * 128;
    float acc[4][8][4] = {};
    gemm2(g_h2h + (size_t)row0 * DD, DD, g_shw1_h + col0, SHH, DD, smem, acc);
    EPI2_SETUP();
#pragma unroll
    for (int mt = 0; mt < 4; mt++)
#pragma unroll
        for (int nt = 0; nt < 8; nt++) {
            int n = col0 + wn * 64 + nt * 8 + 2 * tig;
            float b0 = b1[n], bx = b1[n + 1];
#pragma unroll
            for (int hf = 0; hf < 2; hf++) {
                int m = row0 + wm * 64 + mt * 16 + g + hf * 8;
                *(__half2*)&g_shidh[(size_t)m * SHH + n] =
                    __floats2half2_rn(geluf(acc[mt][nt][2 * hf] + b0),
                                      geluf(acc[mt][nt][2 * hf + 1] + bx));
            }
        }
}

// final split-K chunk c (2 chunks of K=1536): g_part[4+c]
__global__ void __launch_bounds__(128) final_split_g2()
{
    extern __shared__ __half smem[];
    int c = blockIdx.z;
    int row0 = blockIdx.y * 128, col0 = blockIdx.x * 128;
    float acc[4][8][4] = {};
    gemm2(g_shidh + (size_t)row0 * SHH + c * 1536, SHH,
          g_shw2_h + (size_t)(c * 1536) * DD + col0, DD, 1536, smem, acc);
    EPI2_SETUP();
    float* dst = g_part[4 + c];
#pragma unroll
    for (int mt = 0; mt < 4; mt++)
#pragma unroll
        for (int nt = 0; nt < 8; nt++) {
            int n = col0 + wn * 64 + nt * 8 + 2 * tig;
#pragma unroll
            for (int hf = 0; hf < 2; hf++) {
                int m = row0 + wm * 64 + mt * 16 + g + hf * 8;
                *(float2*)&dst[(size_t)m * DD + n] =
                    make_float2(acc[mt][nt][2 * hf], acc[mt][nt][2 * hf + 1]);
            }
        }
}

// ---------------- flash attention (fp16, P in registers) ----------------
#define FLDA 72
#define FLASH_SMEM (3 * 128 * FLDA * 2)

__global__ void __launch_bounds__(256, 1) flash_tc()
{
    extern __shared__ __half hsm[];
    __half* sQ = hsm;
    __half* sK = hsm + 128 * FLDA;
    __half* sV = hsm + 2 * 128 * FLDA;

    const int bh = blockIdx.y;
    const int q0 = blockIdx.x * 128;
    const __half* Qg = g_qh + ((size_t)bh * SS + q0) * DH;
    const __half* Kg = g_kh + (size_t)bh * SS * DH;
    const __half* Vg = g_vh + (size_t)bh * SS * DH;

    const int tid = threadIdx.x, lane = tid & 31, w = tid >> 5;
    const int l16 = lane & 15, lh = lane >> 4;
    const int g = lane >> 2, tig = lane & 3;

#define FCOPY(dst, src)                                                       \
    { _Pragma("unroll")                                                       \
      for (int i = 0; i < 4; i++) {                                           \
          int e = tid + i * 256; int r = e >> 3, v = e & 7;                   \
          cp16h((dst) + r * FLDA + v * 8, (src) + (size_t)r * 64 + v * 8); } }

    FCOPY(sQ, Qg);
    FCOPY(sK, Kg);
    asm volatile("cp.async.commit_group;");
    FCOPY(sV, Vg);
    asm volatile("cp.async.commit_group;");

    float acc_o[8][4] = {};
    float mrun[2] = {-1e30f, -1e30f};
    float lrun[2] = {0.0f, 0.0f};

    const uint32_t sQa = (uint32_t)__cvta_generic_to_shared(sQ);
    const uint32_t sKa = (uint32_t)__cvta_generic_to_shared(sK);
    const uint32_t sVa = (uint32_t)__cvta_generic_to_shared(sV);

    for (int st = 0; st < 4; st++) {
        asm volatile("cp.async.wait_group 1;" ::: "memory");
        __syncthreads();

        float s[16][4] = {};
#pragma unroll
        for (int kk = 0; kk < 4; kk++) {
            int k0 = kk * 16;
            uint32_t a[4];
            ldsm4(a[0], a[1], a[2], a[3],
                  sQa + 2u * ((w * 16 + l16) * FLDA + k0 + lh * 8));
#pragma unroll
            for (int p = 0; p < 8; p++) {
                uint32_t r0, r1, r2, r3;
                ldsm4(r0, r1, r2, r3,
                      sKa + 2u * ((p * 16 + l16) * FLDA + k0 + lh * 8));
                uint32_t b0[2] = {r0, r2}, b1[2] = {r1, r3};
                mma_f16(s[2 * p], a, b0);
                mma_f16(s[2 * p + 1], a, b1);
            }
        }

        float tmax[2] = {-1e30f, -1e30f};
#pragma unroll
        for (int nt = 0; nt < 16; nt++) {
            tmax[0] = fmaxf(tmax[0], fmaxf(s[nt][0], s[nt][1]));
            tmax[1] = fmaxf(tmax[1], fmaxf(s[nt][2], s[nt][3]));
        }
#pragma unroll
        for (int o = 1; o < 4; o <<= 1) {
            tmax[0] = fmaxf(tmax[0], __shfl_xor_sync(0xffffffffu, tmax[0], o));
            tmax[1] = fmaxf(tmax[1], __shfl_xor_sync(0xffffffffu, tmax[1], o));
        }
        float mnew[2], corr[2], rsum[2] = {0.0f, 0.0f};
#pragma unroll
        for (int h = 0; h < 2; h++) {
            mnew[h] = fmaxf(mrun[h], tmax[h] * 0.125f);
            corr[h] = __expf(mrun[h] - mnew[h]);
            mrun[h] = mnew[h];
        }
        uint32_t ph[16][2];
#pragma unroll
        for (int nt = 0; nt < 16; nt++) {
            float p0 = __expf(s[nt][0] * 0.125f - mnew[0]);
            float p1 = __expf(s[nt][1] * 0.125f - mnew[0]);
            float p2 = __expf(s[nt][2] * 0.125f - mnew[1]);
            float p3 = __expf(s[nt][3] * 0.125f - mnew[1]);
            rsum[0] += p0 + p1; rsum[1] += p2 + p3;
            ph[nt][0] = packh2(p0, p1);
            ph[nt][1] = packh2(p2, p3);
        }
#pragma unroll
        for (int o = 1; o < 4; o <<= 1) {
            rsum[0] += __shfl_xor_sync(0xffffffffu, rsum[0], o);
            rsum[1] += __shfl_xor_sync(0xffffffffu, rsum[1], o);
        }
        lrun[0] = lrun[0] * corr[0] + rsum[0];
        lrun[1] = lrun[1] * corr[1] + rsum[1];
#pragma unroll
        for (int nt = 0; nt < 8; nt++) {
            acc_o[nt][0] *= corr[0]; acc_o[nt][1] *= corr[0];
            acc_o[nt][2] *= corr[1]; acc_o[nt][3] *= corr[1];
        }

        asm volatile("cp.async.wait_group 0;" ::: "memory");
        __syncthreads();
        if (st < 3) {
            FCOPY(sK, Kg + (size_t)(st + 1) * 128 * 64);
            asm volatile("cp.async.commit_group;");
        }

#pragma unroll
        for (int j = 0; j < 8; j++) {
            int k0 = j * 16;
            uint32_t a[4] = {ph[2 * j][0], ph[2 * j][1], ph[2 * j + 1][0], ph[2 * j + 1][1]};
#pragma unroll
            for (int p = 0; p < 4; p++) {
                uint32_t r0, r1, r2, r3;
                ldsm4t(r0, r1, r2, r3,
                       sVa + 2u * ((k0 + l16) * FLDA + p * 16 + lh * 8));
                uint32_t b0[2] = {r0, r1}, b1[2] = {r2, r3};
                mma_f16(acc_o[2 * p], a, b0);
                mma_f16(acc_o[2 * p + 1], a, b1);
            }
        }
        __syncthreads();
        if (st < 3) {
            FCOPY(sV, Vg + (size_t)(st + 1) * 128 * 64);
            asm volatile("cp.async.commit_group;");
        }
    }

    const int b = bh / HH, hh = bh - b * HH;
    const float inv0 = 1.0f / lrun[0], inv1 = 1.0f / lrun[1];
    const int m0 = q0 + w * 16 + g;
#pragma unroll
    for (int nt = 0; nt < 8; nt++) {
        int d = nt * 8 + 2 * tig;
        *(__half2*)&g_aoh[((size_t)b * SS + m0) * DD + hh * DH + d] =
            __floats2half2_rn(acc_o[nt][0] * inv0, acc_o[nt][1] * inv0);
        *(__half2*)&g_aoh[((size_t)b * SS + m0 + 8) * DD + hh * DH + d] =
            __floats2half2_rn(acc_o[nt][2] * inv1, acc_o[nt][3] * inv1);
    }
#undef FCOPY
}

// ---------------- conversion kernels ----------------
__global__ void f2h_kernel(const float* __restrict__ in, __half* __restrict__ out, int n8)
{
    int i = blockIdx.x * 256 + threadIdx.x;
    if (i >= n8) return;
    float4 a = ((const float4*)in)[2 * i];
    float4 b = ((const float4*)in)[2 * i + 1];
    uint4 u;
    u.x = packh2(a.x, a.y); u.y = packh2(a.z, a.w);
    u.z = packh2(b.x, b.y); u.w = packh2(b.z, b.w);
    ((uint4*)out)[i] = u;
}

__global__ void expconv_kernel(const float* __restrict__ w1, const float* __restrict__ w2)
{
    int e = blockIdx.y;
    int i = blockIdx.x * 256 + threadIdx.x;
    const int n8 = DD * HID / 8;
    const float* src; __half* dst; int j;
    if (i < n8) { src = w1 + (size_t)e * DD * HID; dst = g_expw1_h + (size_t)e * DD * HID; j = i; }
    else        { src = w2 + (size_t)e * HID * DD; dst = g_expw2_h + (size_t)e * HID * DD; j = i - n8; }
    float4 a = ((const float4*)src)[2 * j];
    float4 b = ((const float4*)src)[2 * j + 1];
    uint4 u;
    u.x = packh2(a.x, a.y); u.y = packh2(a.z, a.w);
    u.z = packh2(b.x, b.y); u.w = packh2(b.z, b.w);
    ((uint4*)dst)[j] = u;
}

// ---------------- elementwise kernels ----------------
__global__ void ln_kernel(const float* __restrict__ in, const float* __restrict__ g,
                          const float* __restrict__ b, __half* __restrict__ outh)
{
    __shared__ float red[256];
    size_t row = blockIdx.x;
    const float* xr = in + row * DD;
    int tid = threadIdx.x;
    float x0 = xr[tid], x1 = xr[tid + 256], x2 = xr[tid + 512];
    float total = blockReduceSum(x0 + x1 + x2, red);
    float mean = total * (1.0f / DD);
    float d0 = x0 - mean, d1 = x1 - mean, d2 = x2 - mean;
    float var = blockReduceSum(d0 * d0 + d1 * d1 + d2 * d2, red) * (1.0f / DD);
    float rstd = rsqrtf(var + 1e-5f);
    outh[row * DD + tid]       = __float2half_rn(d0 * rstd * g[tid]       + b[tid]);
    outh[row * DD + tid + 256] = __float2half_rn(d1 * rstd * g[tid + 256] + b[tid + 256]);
    outh[row * DD + tid + 512] = __float2half_rn(d2 * rstd * g[tid + 512] + b[tid + 512]);
}

// seq_repr from fp16 h2 (fp32 accumulate)
__global__ void seqmean_kernel()
{
    int b = blockIdx.y;
    int d = blockIdx.x * 256 + threadIdx.x;
    const __half* p = g_h2h + (size_t)b * SS * DD + d;
    float s = 0.0f;
    for (int i = 0; i < SS; i++) s += __half2float(p[(size_t)i * DD]);
    g_seq[b * DD + d] = s * (1.0f / SS);
}

__global__ void router_kernel(const float* __restrict__ w1, const float* __restrict__ b1,
                              const float* __restrict__ w2, const float* __restrict__ b2)
{
    __shared__ float s_in[DD];
    __shared__ float s_hid[DD];
    __shared__ float s_logits[EE];
    int b = blockIdx.x;
    int tid = threadIdx.x;
    for (int i = tid; i < DD; i += 256) s_in[i] = g_seq[b * DD + i];
    __syncthreads();
    for (int j = tid; j < DD; j += 256) {
        float a = b1[j];
        for (int d = 0; d < DD; d++) a = fmaf(s_in[d], w1[(size_t)d * DD + j], a);
        s_hid[j] = geluf(a);
    }
    __syncthreads();
    if (tid < EE) {
        float a = b2[tid];
        for (int d = 0; d < DD; d++) a = fmaf(s_hid[d], w2[(size_t)d * EE + tid], a);
        s_logits[tid] = a;
    }
    __syncthreads();
    if (tid == 0) {
        float p[EE];
        float mx = -1e30f;
        for (int e = 0; e < EE; e++) mx = fmaxf(mx, s_logits[e]);
        float sum = 0.0f;
        for (int e = 0; e < EE; e++) { p[e] = expf(s_logits[e] - mx); sum += p[e]; }
        float inv = 1.0f / sum;
        for (int e = 0; e < EE; e++) p[e] *= inv;
        int   idx[KK];
        float val[KK];
        bool used[EE] = {};
        for (int k = 0; k < KK; k++) {
            int best = -1; float bv = -1e30f;
            for (int e = 0; e < EE; e++)
                if (!used[e] && p[e] > bv) { bv = p[e]; best = e; }
            used[best] = true; idx[k] = best; val[k] = bv;
        }
        float m2 = val[0];
        float s2 = 0.0f, tw[KK];
        for (int k = 0; k < KK; k++) { tw[k] = expf(val[k] - m2); s2 += tw[k]; }
        float inv2 = 1.0f / s2;
        for (int e = 0; e < EE; e++) g_wgt[b * EE + e] = 0.0f;
        for (int k = 0; k < KK; k++) g_wgt[b * EE + idx[k]] = tw[k] * inv2;
    }
}

__global__ void final_sum_kernel(const float* __restrict__ b2, float* __restrict__ out)
{
    int i = blockIdx.x * 256 + threadIdx.x;
    int n = (i % (DD / 4)) * 4;
    float4 r = *(const float4*)(g_x2 + (size_t)i * 4);
#pragma unroll
    for (int j = 0; j < 6; j++) {
        float4 p = *(const float4*)(g_part[j] + (size_t)i * 4);
        r.x += p.x; r.y += p.y; r.z += p.z; r.w += p.w;
    }
    float4 bb = *(const float4*)(b2 + n);
    r.x += bb.x; r.y += bb.y; r.z += bb.z; r.w += bb.w;
    *(float4*)(out + (size_t)i * 4) = r;
}

// ---------------- launch ----------------
extern "C" void kernel_launch(void* const* d_in, const int* in_sizes, int n_in,
                              void* d_out, int out_size)
{
    const float* x         = (const float*)d_in[0];
    const float* ln1_g     = (const float*)d_in[1];
    const float* ln1_b     = (const float*)d_in[2];
    const float* qkv_w     = (const float*)d_in[3];
    const float* proj_w    = (const float*)d_in[4];
    const float* proj_b    = (const float*)d_in[5];
    const float* ln2_g     = (const float*)d_in[6];
    const float* ln2_b     = (const float*)d_in[7];
    const float* router_w1 = (const float*)d_in[8];
    const float* router_b1 = (const float*)d_in[9];
    const float* router_w2 = (const float*)d_in[10];
    const float* router_b2 = (const float*)d_in[11];
    const float* exp_w1    = (const float*)d_in[12];
    const float* exp_b1    = (const float*)d_in[13];
    const float* exp_w2    = (const float*)d_in[14];
    const float* exp_b2    = (const float*)d_in[15];
    const float* sh_w1     = (const float*)d_in[16];
    const float* sh_b1     = (const float*)d_in[17];
    const float* sh_w2     = (const float*)d_in[18];
    const float* sh_b2     = (const float*)d_in[19];
    float* out = (float*)d_out;

    static cudaStream_t sW = nullptr, sB = nullptr;
    static cudaEvent_t evF1 = nullptr, evWq = nullptr, evW = nullptr, evWX = nullptr,
                       evF2 = nullptr, evB = nullptr;
    if (!sW) {
        cudaStreamCreateWithFlags(&sW, cudaStreamNonBlocking);
        cudaStreamCreateWithFlags(&sB, cudaStreamNonBlocking);
        cudaEventCreateWithFlags(&evF1, cudaEventDisableTiming);
        cudaEventCreateWithFlags(&evWq, cudaEventDisableTiming);
        cudaEventCreateWithFlags(&evW,  cudaEventDisableTiming);
        cudaEventCreateWithFlags(&evWX, cudaEventDisableTiming);
        cudaEventCreateWithFlags(&evF2, cudaEventDisableTiming);
        cudaEventCreateWithFlags(&evB,  cudaEventDisableTiming);
    }

    cudaFuncSetAttribute(qkv_g2,        cudaFuncAttributeMaxDynamicSharedMemorySize, SMEMB_G2);
    cudaFuncSetAttribute(proj_g2,       cudaFuncAttributeMaxDynamicSharedMemorySize, SMEMB_G2);
    cudaFuncSetAttribute(expert_hid_g2, cudaFuncAttributeMaxDynamicSharedMemorySize, SMEMB_G2);
    cudaFuncSetAttribute(expert_out_g2, cudaFuncAttributeMaxDynamicSharedMemorySize, SMEMB_G2);
    cudaFuncSetAttribute(shared_hid_g2, cudaFuncAttributeMaxDynamicSharedMemorySize, SMEMB_G2);
    cudaFuncSetAttribute(final_split_g2,cudaFuncAttributeMaxDynamicSharedMemorySize, SMEMB_G2);
    cudaFuncSetAttribute(flash_tc,      cudaFuncAttributeMaxDynamicSharedMemorySize, FLASH_SMEM);

    __half* wq;  cudaGetSymbolAddress((void**)&wq,  g_qkvw_h);
    __half* wp;  cudaGetSymbolAddress((void**)&wp,  g_projw_h);
    __half* w1;  cudaGetSymbolAddress((void**)&w1,  g_shw1_h);
    __half* w2;  cudaGetSymbolAddress((void**)&w2,  g_shw2_h);
    __half* h1h; cudaGetSymbolAddress((void**)&h1h, g_h1h);
    __half* h2h; cudaGetSymbolAddress((void**)&h2h, g_h2h);
    float*  x2;  cudaGetSymbolAddress((void**)&x2,  g_x2);

    // fork sW: qkv weight FIRST (unblocks the first GEMM asap), then the rest
    cudaEventRecord(evF1, 0);
    cudaStreamWaitEvent(sW, evF1, 0);
    f2h_kernel<<<(DD*3*DD/8 + 255)/256, 256, 0, sW>>>(qkv_w, wq, DD*3*DD/8);
    cudaEventRecord(evWq, sW);
    f2h_kernel<<<(DD*DD/8   + 255)/256, 256, 0, sW>>>(proj_w, wp, DD*DD/8);
    f2h_kernel<<<(DD*SHH/8  + 255)/256, 256, 0, sW>>>(sh_w1, w1, DD*SHH/8);
    f2h_kernel<<<(SHH*DD/8  + 255)/256, 256, 0, sW>>>(sh_w2, w2, SHH*DD/8);
    cudaEventRecord(evW, sW);
    expconv_kernel<<<dim3(2*DD*HID/8/256, EE), 256, 0, sW>>>(exp_w1, exp_w2);
    cudaEventRecord(evWX, sW);

    // attention branch (main stream)
    ln_kernel<<<NTOK, 256>>>(x, ln1_g, ln1_b, h1h);
    cudaStreamWaitEvent(0, evWq, 0);
    qkv_g2<<<dim3(18, 32), 128, SMEMB_G2>>>();
    flash_tc<<<dim3(4, BHN), 256, FLASH_SMEM>>>();
    cudaStreamWaitEvent(0, evW, 0);       // proj weight (long since done)
    proj_g2<<<dim3(6, 32), 128, SMEMB_G2>>>(proj_b, x);

    // ln2 -> fork shared-expert chain onto sB (sB waits shared weights too)
    ln_kernel<<<NTOK, 256>>>(x2, ln2_g, ln2_b, h2h);
    cudaEventRecord(evF2, 0);
    cudaStreamWaitEvent(sB, evF2, 0);
    cudaStreamWaitEvent(sB, evW, 0);
    shared_hid_g2<<<dim3(24, 32), 128, SMEMB_G2, sB>>>(sh_b1);
    final_split_g2<<<dim3(6, 32, 2), 128, SMEMB_G2, sB>>>();
    cudaEventRecord(evB, sB);

    // routed-expert chain (main stream, overlaps sB)
    seqmean_kernel<<<dim3(3, BB), 256>>>();
    router_kernel<<<BB, 256>>>(router_w1, router_b1, router_w2, router_b2);
    cudaStreamWaitEvent(0, evWX, 0);
    expert_hid_g2<<<dim3(12, 4, BB * KK), 128, SMEMB_G2>>>(exp_b1);
    expert_out_g2<<<dim3(6, 4, BB * KK), 128, SMEMB_G2>>>(exp_b2);

    // join and reduce
    cudaStreamWaitEvent(0, evB, 0);
    final_sum_kernel<<<NTOK * DD / 4 / 256, 256>>>(sh_b2, out);
}

// round 15
// speedup vs baseline: 1.1584x; 1.0689x over previous
#include <cuda_runtime.h>
#include <cuda_fp16.h>
#include <cstdint>
#include <math.h>

// ---------------- problem constants ----------------
#define BB   8
#define SS   512
#define DD   768
#define HH   12
#define DH   64
#define EE   14
#define KK   4
#define HID  1536
#define SHH  3072
#define NTOK (BB*SS)          // 4096
#define BHN  (BB*HH)          // 96

// ---------------- scratch (device globals; no allocation) ----------------
__device__ __align__(128) __half g_h1h [(size_t)NTOK*DD];
__device__ __align__(128) __half g_qh  [(size_t)BHN*SS*DH];
__device__ __align__(128) __half g_kh  [(size_t)BHN*SS*DH];
__device__ __align__(128) __half g_vh  [(size_t)BHN*SS*DH];
__device__ __align__(128) __half g_aoh [(size_t)NTOK*DD];
__device__ __align__(128) float  g_x2  [(size_t)NTOK*DD];
__device__ __align__(128) __half g_h2h [(size_t)NTOK*DD];
__device__ __align__(128) float  g_wgt [(size_t)BB*EE];
__device__ __align__(128) __half g_ehidh[(size_t)EE*BB*SS*HID];
__device__ __align__(128) __half g_shidh[(size_t)NTOK*SHH];
__device__ __align__(128) float  g_part[6][(size_t)NTOK*DD];   // 0..3 expert slots, 4..5 final
// fp16 weight mirrors, [K][N] row-major
__device__ __align__(128) __half g_qkvw_h [(size_t)DD*3*DD];
__device__ __align__(128) __half g_projw_h[(size_t)DD*DD];
__device__ __align__(128) __half g_shw1_h [(size_t)DD*SHH];
__device__ __align__(128) __half g_shw2_h [(size_t)SHH*DD];
__device__ __align__(128) __half g_expw1_h[(size_t)EE*DD*HID];
__device__ __align__(128) __half g_expw2_h[(size_t)EE*HID*DD];

// ---------------- helpers ----------------
__device__ __forceinline__ float geluf(float x) {
    return 0.5f * x * (1.0f + erff(x * 0.70710678118654752f));
}
__device__ __forceinline__ uint32_t packh2(float a, float b) {
    __half2 h = __floats2half2_rn(a, b);
    return *(uint32_t*)&h;
}
__device__ __forceinline__ void cp16h(__half* dst_smem, const __half* src) {
    uint32_t d = (uint32_t)__cvta_generic_to_shared(dst_smem);
    asm volatile("cp.async.cg.shared.global [%0], [%1], 16;" :: "r"(d), "l"(src));
}
__device__ __forceinline__ void ldsm4(uint32_t &r0, uint32_t &r1, uint32_t &r2, uint32_t &r3,
                                      uint32_t addr) {
    asm volatile("ldmatrix.sync.aligned.m8n8.x4.shared.b16 {%0,%1,%2,%3}, [%4];"
                 : "=r"(r0), "=r"(r1), "=r"(r2), "=r"(r3) : "r"(addr));
}
__device__ __forceinline__ void ldsm4t(uint32_t &r0, uint32_t &r1, uint32_t &r2, uint32_t &r3,
                                       uint32_t addr) {
    asm volatile("ldmatrix.sync.aligned.m8n8.x4.trans.shared.b16 {%0,%1,%2,%3}, [%4];"
                 : "=r"(r0), "=r"(r1), "=r"(r2), "=r"(r3) : "r"(addr));
}
__device__ __forceinline__ void mma_f16(float c[4], const uint32_t a[4], const uint32_t b[2]) {
    asm volatile("mma.sync.aligned.m16n8k16.row.col.f32.f16.f16.f32 "
                 "{%0,%1,%2,%3}, {%4,%5,%6,%7}, {%8,%9}, {%0,%1,%2,%3};"
                 : "+f"(c[0]), "+f"(c[1]), "+f"(c[2]), "+f"(c[3])
                 : "r"(a[0]), "r"(a[1]), "r"(a[2]), "r"(a[3]), "r"(b[0]), "r"(b[1]));
}

__device__ __forceinline__ float blockReduceSum(float v, float* sh) {
    int tid = threadIdx.x;
    sh[tid] = v; __syncthreads();
    for (int s = 128; s > 0; s >>= 1) {
        if (tid < s) sh[tid] += sh[tid + s];
        __syncthreads();
    }
    float r = sh[0]; __syncthreads();
    return r;
}

// ======================================================================
// fp16 GEMM core: 128 threads / 4 warps, warp tile 64x64, CTA 128x128,
// BK=64, 3-stage cp.async, one barrier per 64 k-elements, register
// double-buffered fragments.
// ======================================================================
#define G2_LDA 72
#define G2_LDB 136
#define G2_ASZ (128*G2_LDA)
#define G2_BSZ (64*G2_LDB)
#define G2_STG (G2_ASZ + G2_BSZ)          // 17920 halves = 35840 B
#define SMEMB_G2 (3 * G2_STG * 2)         // 107520 B

__device__ __forceinline__ void gemm2(const __half* __restrict__ A, int lda,
                                      const __half* __restrict__ B, int ldb,
                                      int K, __half* smem, float acc[4][8][4])
{
    const int tid  = threadIdx.x;         // 128
    const int lane = tid & 31;
    const int w    = tid >> 5;
    const int wm   = w >> 1;
    const int wn   = w & 1;
    const int l16  = lane & 15;
    const int lh   = lane >> 4;

#define G2_LOAD(kt, stg)                                                     \
    { __half* bA = smem + (stg) * G2_STG;                                    \
      __half* bBp = bA + G2_ASZ;                                             \
      _Pragma("unroll")                                                      \
      for (int i = 0; i < 8; i++) {                                          \
          int e = tid + i * 128; int row = e >> 3, v = e & 7;                \
          cp16h(bA + row * G2_LDA + v * 8, A + (size_t)row * lda + (kt) + v * 8); } \
      _Pragma("unroll")                                                      \
      for (int i = 0; i < 8; i++) {                                          \
          int e = tid + i * 128; int row = e >> 4, v = e & 15;               \
          cp16h(bBp + row * G2_LDB + v * 8, B + (size_t)((kt) + row) * ldb + v * 8); } }

#define G2_FRAG(kk, buf, aB, bBa)                                            \
    { int k0 = (kk) * 16;                                                    \
      _Pragma("unroll")                                                      \
      for (int mt = 0; mt < 4; mt++)                                         \
          ldsm4(a[buf][mt][0], a[buf][mt][1], a[buf][mt][2], a[buf][mt][3],  \
                (aB) + 2u * ((wm * 64 + mt * 16 + l16) * G2_LDA + k0 + lh * 8)); \
      _Pragma("unroll")                                                      \
      for (int p = 0; p < 4; p++) {                                          \
          uint32_t r0, r1, r2, r3;                                           \
          ldsm4t(r0, r1, r2, r3,                                             \
                 (bBa) + 2u * ((k0 + l16) * G2_LDB + wn * 64 + p * 16 + lh * 8)); \
          b[buf][2 * p][0] = r0; b[buf][2 * p][1] = r1;                      \
          b[buf][2 * p + 1][0] = r2; b[buf][2 * p + 1][1] = r3; } }

    const int nst = K / 64;
    G2_LOAD(0, 0);
    asm volatile("cp.async.commit_group;");
    G2_LOAD(64, 1);
    asm volatile("cp.async.commit_group;");

    uint32_t a[2][4][4], b[2][8][2];

    int stg = 0;
    for (int t = 0; t < nst; t++) {
        if (t + 1 < nst) asm volatile("cp.async.wait_group 1;" ::: "memory");
        else             asm volatile("cp.async.wait_group 0;" ::: "memory");
        __syncthreads();
        if (t + 2 < nst) {
            int ns = stg + 2; if (ns >= 3) ns -= 3;
            G2_LOAD((t + 2) * 64, ns);
            asm volatile("cp.async.commit_group;");
        }
        __half* cA = smem + stg * G2_STG;
        uint32_t aB = (uint32_t)__cvta_generic_to_shared(cA);
        uint32_t bBa = (uint32_t)__cvta_generic_to_shared(cA + G2_ASZ);

        G2_FRAG(0, 0, aB, bBa);
#pragma unroll
        for (int kk = 0; kk < 4; kk++) {
            if (kk < 3) G2_FRAG(kk + 1, (kk + 1) & 1, aB, bBa);
#pragma unroll
            for (int mt = 0; mt < 4; mt++)
#pragma unroll
                for (int nt = 0; nt < 8; nt++)
                    mma_f16(acc[mt][nt], a[kk & 1][mt], b[kk & 1][nt]);
        }
        if (++stg == 3) stg = 0;
    }
#undef G2_LOAD
#undef G2_FRAG
}

#define EPI2_SETUP()                                            \
    const int tid = threadIdx.x;                                \
    const int lane = tid & 31, w = tid >> 5;                    \
    const int wm = w >> 1, wn = w & 1;                          \
    const int g = lane >> 2, tig = lane & 3;

// ---------------- gemm2 kernels (128 threads each) ----------------

__global__ void __launch_bounds__(128) qkv_g2()
{
    extern __shared__ __half smem[];
    int row0 = blockIdx.y * 128, col0 = blockIdx.x * 128;
    float acc[4][8][4] = {};
    gemm2(g_h1h + (size_t)row0 * DD, DD, g_qkvw_h + col0, 3 * DD, DD, smem, acc);
    EPI2_SETUP();
#pragma unroll
    for (int mt = 0; mt < 4; mt++)
#pragma unroll
        for (int nt = 0; nt < 8; nt++) {
            int n = col0 + wn * 64 + nt * 8 + 2 * tig;
            int which = n / DD;
            int rem = n - which * DD;
            int h = rem >> 6, d = rem & 63;
            __half* dst = (which == 0) ? g_qh : ((which == 1) ? g_kh : g_vh);
#pragma unroll
            for (int hf = 0; hf < 2; hf++) {
                int m = row0 + wm * 64 + mt * 16 + g + hf * 8;
                int b = m >> 9, s = m & 511;
                *(__half2*)&dst[(((size_t)b * HH + h) * SS + s) * DH + d] =
                    __floats2half2_rn(acc[mt][nt][2 * hf], acc[mt][nt][2 * hf + 1]);
            }
        }
}

__global__ void __launch_bounds__(128) proj_g2(const float* __restrict__ bias,
                                               const float* __restrict__ x)
{
    extern __shared__ __half smem[];
    int row0 = blockIdx.y * 128, col0 = blockIdx.x * 128;
    float acc[4][8][4] = {};
    gemm2(g_aoh + (size_t)row0 * DD, DD, g_projw_h + col0, DD, DD, smem, acc);
    EPI2_SETUP();
#pragma unroll
    for (int mt = 0; mt < 4; mt++)
#pragma unroll
        for (int nt = 0; nt < 8; nt++) {
            int n = col0 + wn * 64 + nt * 8 + 2 * tig;
            float b0 = bias[n], b1 = bias[n + 1];
#pragma unroll
            for (int hf = 0; hf < 2; hf++) {
                int m = row0 + wm * 64 + mt * 16 + g + hf * 8;
                size_t idx = (size_t)m * DD + n;
                float2 xv = *(const float2*)&x[idx];
                *(float2*)&g_x2[idx] =
                    make_float2(xv.x + acc[mt][nt][2 * hf] + b0,
                                xv.y + acc[mt][nt][2 * hf + 1] + b1);
            }
        }
}

// expert hidden, slot-parallel (z = b*KK + slot, 32 slices, all active)
__global__ void __launch_bounds__(128) expert_hid_g2(const float* __restrict__ b1)
{
    extern __shared__ __half smem[];
    int b = blockIdx.z >> 2, slot = blockIdx.z & 3;
    int e = 0; float wv = 0.0f;
    {
        int cnt = -1;
        for (int j = 0; j < EE; j++) {
            float t = g_wgt[b * EE + j];
            if (t != 0.0f) { cnt++; if (cnt == slot) { e = j; wv = t; break; } }
        }
    }
    int row0 = blockIdx.y * 128, col0 = blockIdx.x * 128;
    float acc[4][8][4] = {};
    gemm2(g_h2h + ((size_t)b * SS + row0) * DD, DD,
          g_expw1_h + (size_t)e * DD * HID + col0, HID, DD, smem, acc);
    EPI2_SETUP();
    __half* dst = g_ehidh + ((size_t)e * BB + b) * SS * HID;
#pragma unroll
    for (int mt = 0; mt < 4; mt++)
#pragma unroll
        for (int nt = 0; nt < 8; nt++) {
            int n = col0 + wn * 64 + nt * 8 + 2 * tig;
            float b0 = b1[e * HID + n], bx = b1[e * HID + n + 1];
#pragma unroll
            for (int hf = 0; hf < 2; hf++) {
                int m = row0 + wm * 64 + mt * 16 + g + hf * 8;
                *(__half2*)&dst[(size_t)m * HID + n] =
                    __floats2half2_rn(wv * geluf(acc[mt][nt][2 * hf] + b0),
                                      wv * geluf(acc[mt][nt][2 * hf + 1] + bx));
            }
        }
}

// expert out, slot-parallel: one block set per (b, slot) -> g_part[slot]
__global__ void __launch_bounds__(128) expert_out_g2(const float* __restrict__ b2)
{
    extern __shared__ __half smem[];
    int b = blockIdx.z >> 2, slot = blockIdx.z & 3;
    int e = 0; float wv = 0.0f;
    {
        int cnt = -1;
        for (int j = 0; j < EE; j++) {
            float t = g_wgt[b * EE + j];
            if (t != 0.0f) { cnt++; if (cnt == slot) { e = j; wv = t; break; } }
        }
    }
    int row0 = blockIdx.y * 128, col0 = blockIdx.x * 128;
    float acc[4][8][4] = {};
    gemm2(g_ehidh + (((size_t)e * BB + b) * SS + row0) * HID, HID,
          g_expw2_h + (size_t)e * HID * DD + col0, DD, HID, smem, acc);
    EPI2_SETUP();
    float* dst = g_part[slot];
#pragma unroll
    for (int mt = 0; mt < 4; mt++)
#pragma unroll
        for (int nt = 0; nt < 8; nt++) {
            int n = col0 + wn * 64 + nt * 8 + 2 * tig;
            float b0 = wv * b2[e * DD + n], b1v = wv * b2[e * DD + n + 1];
#pragma unroll
            for (int hf = 0; hf < 2; hf++) {
                int m = row0 + wm * 64 + mt * 16 + g + hf * 8;
                *(float2*)&dst[((size_t)b * SS + m) * DD + n] =
                    make_float2(acc[mt][nt][2 * hf] + b0,
                                acc[mt][nt][2 * hf + 1] + b1v);
            }
        }
}

__global__ void __launch_bounds__(128) shared_hid_g2(const float* __restrict__ b1)
{
    extern __shared__ __half smem[];
    int row0 = blockIdx.y * 128, col0 = blockIdx.x * 128;
    float acc[4][8][4] = {};
    gemm2(g_h2h + (size_t)row0 * DD, DD, g_shw1_h + col0, SHH, DD, smem, acc);
    EPI2_SETUP();
#pragma unroll
    for (int mt = 0; mt < 4; mt++)
#pragma unroll
        for (int nt = 0; nt < 8; nt++) {
            int n = col0 + wn * 64 + nt * 8 + 2 * tig;
            float b0 = b1[n], bx = b1[n + 1];
#pragma unroll
            for (int hf = 0; hf < 2; hf++) {
                int m = row0 + wm * 64 + mt * 16 + g + hf * 8;
                *(__half2*)&g_shidh[(size_t)m * SHH + n] =
                    __floats2half2_rn(geluf(acc[mt][nt][2 * hf] + b0),
                                      geluf(acc[mt][nt][2 * hf + 1] + bx));
            }
        }
}

// final split-K chunk c (2 chunks of K=1536): g_part[4+c]
__global__ void __launch_bounds__(128) final_split_g2()
{
    extern __shared__ __half smem[];
    int c = blockIdx.z;
    int row0 = blockIdx.y * 128, col0 = blockIdx.x * 128;
    float acc[4][8][4] = {};
    gemm2(g_shidh + (size_t)row0 * SHH + c * 1536, SHH,
          g_shw2_h + (size_t)(c * 1536) * DD + col0, DD, 1536, smem, acc);
    EPI2_SETUP();
    float* dst = g_part[4 + c];
#pragma unroll
    for (int mt = 0; mt < 4; mt++)
#pragma unroll
        for (int nt = 0; nt < 8; nt++) {
            int n = col0 + wn * 64 + nt * 8 + 2 * tig;
#pragma unroll
            for (int hf = 0; hf < 2; hf++) {
                int m = row0 + wm * 64 + mt * 16 + g + hf * 8;
                *(float2*)&dst[(size_t)m * DD + n] =
                    make_float2(acc[mt][nt][2 * hf], acc[mt][nt][2 * hf + 1]);
            }
        }
}

// ---------------- flash attention (fp16, P in registers) ----------------
#define FLDA 72
#define FLASH_SMEM (3 * 128 * FLDA * 2)

__global__ void __launch_bounds__(256, 1) flash_tc()
{
    extern __shared__ __half hsm[];
    __half* sQ = hsm;
    __half* sK = hsm + 128 * FLDA;
    __half* sV = hsm + 2 * 128 * FLDA;

    const int bh = blockIdx.y;
    const int q0 = blockIdx.x * 128;
    const __half* Qg = g_qh + ((size_t)bh * SS + q0) * DH;
    const __half* Kg = g_kh + (size_t)bh * SS * DH;
    const __half* Vg = g_vh + (size_t)bh * SS * DH;

    const int tid = threadIdx.x, lane = tid & 31, w = tid >> 5;
    const int l16 = lane & 15, lh = lane >> 4;
    const int g = lane >> 2, tig = lane & 3;

#define FCOPY(dst, src)                                                       \
    { _Pragma("unroll")                                                       \
      for (int i = 0; i < 4; i++) {                                           \
          int e = tid + i * 256; int r = e >> 3, v = e & 7;                   \
          cp16h((dst) + r * FLDA + v * 8, (src) + (size_t)r * 64 + v * 8); } }

    FCOPY(sQ, Qg);
    FCOPY(sK, Kg);
    asm volatile("cp.async.commit_group;");
    FCOPY(sV, Vg);
    asm volatile("cp.async.commit_group;");

    float acc_o[8][4] = {};
    float mrun[2] = {-1e30f, -1e30f};
    float lrun[2] = {0.0f, 0.0f};

    const uint32_t sQa = (uint32_t)__cvta_generic_to_shared(sQ);
    const uint32_t sKa = (uint32_t)__cvta_generic_to_shared(sK);
    const uint32_t sVa = (uint32_t)__cvta_generic_to_shared(sV);

    for (int st = 0; st < 4; st++) {
        asm volatile("cp.async.wait_group 1;" ::: "memory");
        __syncthreads();

        float s[16][4] = {};
#pragma unroll
        for (int kk = 0; kk < 4; kk++) {
            int k0 = kk * 16;
            uint32_t a[4];
            ldsm4(a[0], a[1], a[2], a[3],
                  sQa + 2u * ((w * 16 + l16) * FLDA + k0 + lh * 8));
#pragma unroll
            for (int p = 0; p < 8; p++) {
                uint32_t r0, r1, r2, r3;
                ldsm4(r0, r1, r2, r3,
                      sKa + 2u * ((p * 16 + l16) * FLDA + k0 + lh * 8));
                uint32_t b0[2] = {r0, r2}, b1[2] = {r1, r3};
                mma_f16(s[2 * p], a, b0);
                mma_f16(s[2 * p + 1], a, b1);
            }
        }

        float tmax[2] = {-1e30f, -1e30f};
#pragma unroll
        for (int nt = 0; nt < 16; nt++) {
            tmax[0] = fmaxf(tmax[0], fmaxf(s[nt][0], s[nt][1]));
            tmax[1] = fmaxf(tmax[1], fmaxf(s[nt][2], s[nt][3]));
        }
#pragma unroll
        for (int o = 1; o < 4; o <<= 1) {
            tmax[0] = fmaxf(tmax[0], __shfl_xor_sync(0xffffffffu, tmax[0], o));
            tmax[1] = fmaxf(tmax[1], __shfl_xor_sync(0xffffffffu, tmax[1], o));
        }
        float mnew[2], corr[2], rsum[2] = {0.0f, 0.0f};
#pragma unroll
        for (int h = 0; h < 2; h++) {
            mnew[h] = fmaxf(mrun[h], tmax[h] * 0.125f);
            corr[h] = __expf(mrun[h] - mnew[h]);
            mrun[h] = mnew[h];
        }
        uint32_t ph[16][2];
#pragma unroll
        for (int nt = 0; nt < 16; nt++) {
            float p0 = __expf(s[nt][0] * 0.125f - mnew[0]);
            float p1 = __expf(s[nt][1] * 0.125f - mnew[0]);
            float p2 = __expf(s[nt][2] * 0.125f - mnew[1]);
            float p3 = __expf(s[nt][3] * 0.125f - mnew[1]);
            rsum[0] += p0 + p1; rsum[1] += p2 + p3;
            ph[nt][0] = packh2(p0, p1);
            ph[nt][1] = packh2(p2, p3);
        }
#pragma unroll
        for (int o = 1; o < 4; o <<= 1) {
            rsum[0] += __shfl_xor_sync(0xffffffffu, rsum[0], o);
            rsum[1] += __shfl_xor_sync(0xffffffffu, rsum[1], o);
        }
        lrun[0] = lrun[0] * corr[0] + rsum[0];
        lrun[1] = lrun[1] * corr[1] + rsum[1];
#pragma unroll
        for (int nt = 0; nt < 8; nt++) {
            acc_o[nt][0] *= corr[0]; acc_o[nt][1] *= corr[0];
            acc_o[nt][2] *= corr[1]; acc_o[nt][3] *= corr[1];
        }

        asm volatile("cp.async.wait_group 0;" ::: "memory");
        __syncthreads();
        if (st < 3) {
            FCOPY(sK, Kg + (size_t)(st + 1) * 128 * 64);
            asm volatile("cp.async.commit_group;");
        }

#pragma unroll
        for (int j = 0; j < 8; j++) {
            int k0 = j * 16;
            uint32_t a[4] = {ph[2 * j][0], ph[2 * j][1], ph[2 * j + 1][0], ph[2 * j + 1][1]};
#pragma unroll
            for (int p = 0; p < 4; p++) {
                uint32_t r0, r1, r2, r3;
                ldsm4t(r0, r1, r2, r3,
                       sVa + 2u * ((k0 + l16) * FLDA + p * 16 + lh * 8));
                uint32_t b0[2] = {r0, r1}, b1[2] = {r2, r3};
                mma_f16(acc_o[2 * p], a, b0);
                mma_f16(acc_o[2 * p + 1], a, b1);
            }
        }
        __syncthreads();
        if (st < 3) {
            FCOPY(sV, Vg + (size_t)(st + 1) * 128 * 64);
            asm volatile("cp.async.commit_group;");
        }
    }

    const int b = bh / HH, hh = bh - b * HH;
    const float inv0 = 1.0f / lrun[0], inv1 = 1.0f / lrun[1];
    const int m0 = q0 + w * 16 + g;
#pragma unroll
    for (int nt = 0; nt < 8; nt++) {
        int d = nt * 8 + 2 * tig;
        *(__half2*)&g_aoh[((size_t)b * SS + m0) * DD + hh * DH + d] =
            __floats2half2_rn(acc_o[nt][0] * inv0, acc_o[nt][1] * inv0);
        *(__half2*)&g_aoh[((size_t)b * SS + m0 + 8) * DD + hh * DH + d] =
            __floats2half2_rn(acc_o[nt][2] * inv1, acc_o[nt][3] * inv1);
    }
#undef FCOPY
}

// ---------------- conversion kernels ----------------
__global__ void f2h_kernel(const float* __restrict__ in, __half* __restrict__ out, int n8)
{
    int i = blockIdx.x * 256 + threadIdx.x;
    if (i >= n8) return;
    float4 a = ((const float4*)in)[2 * i];
    float4 b = ((const float4*)in)[2 * i + 1];
    uint4 u;
    u.x = packh2(a.x, a.y); u.y = packh2(a.z, a.w);
    u.z = packh2(b.x, b.y); u.w = packh2(b.z, b.w);
    ((uint4*)out)[i] = u;
}

__global__ void expconv_kernel(const float* __restrict__ w1, const float* __restrict__ w2)
{
    int e = blockIdx.y;
    int i = blockIdx.x * 256 + threadIdx.x;
    const int n8 = DD * HID / 8;
    const float* src; __half* dst; int j;
    if (i < n8) { src = w1 + (size_t)e * DD * HID; dst = g_expw1_h + (size_t)e * DD * HID; j = i; }
    else        { src = w2 + (size_t)e * HID * DD; dst = g_expw2_h + (size_t)e * HID * DD; j = i - n8; }
    float4 a = ((const float4*)src)[2 * j];
    float4 b = ((const float4*)src)[2 * j + 1];
    uint4 u;
    u.x = packh2(a.x, a.y); u.y = packh2(a.z, a.w);
    u.z = packh2(b.x, b.y); u.w = packh2(b.z, b.w);
    ((uint4*)dst)[j] = u;
}

// ---------------- elementwise kernels ----------------
__global__ void ln_kernel(const float* __restrict__ in, const float* __restrict__ g,
                          const float* __restrict__ b, __half* __restrict__ outh)
{
    __shared__ float red[256];
    size_t row = blockIdx.x;
    const float* xr = in + row * DD;
    int tid = threadIdx.x;
    float x0 = xr[tid], x1 = xr[tid + 256], x2 = xr[tid + 512];
    float total = blockReduceSum(x0 + x1 + x2, red);
    float mean = total * (1.0f / DD);
    float d0 = x0 - mean, d1 = x1 - mean, d2 = x2 - mean;
    float var = blockReduceSum(d0 * d0 + d1 * d1 + d2 * d2, red) * (1.0f / DD);
    float rstd = rsqrtf(var + 1e-5f);
    outh[row * DD + tid]       = __float2half_rn(d0 * rstd * g[tid]       + b[tid]);
    outh[row * DD + tid + 256] = __float2half_rn(d1 * rstd * g[tid + 256] + b[tid + 256]);
    outh[row * DD + tid + 512] = __float2half_rn(d2 * rstd * g[tid + 512] + b[tid + 512]);
}

// fused seq-mean + router MLP + top-4: one block per batch
__global__ void router_kernel(const float* __restrict__ w1, const float* __restrict__ b1,
                              const float* __restrict__ w2, const float* __restrict__ b2)
{
    __shared__ float s_in[DD];
    __shared__ float s_hid[DD];
    __shared__ float s_logits[EE];
    int b = blockIdx.x;
    int tid = threadIdx.x;
    // seq mean over 512 rows, 3 dims per thread, fp32 accumulate from fp16
    {
        const __half* base = g_h2h + (size_t)b * SS * DD;
        float a0 = 0.0f, a1 = 0.0f, a2 = 0.0f;
        for (int i = 0; i < SS; i++) {
            const __half* r = base + (size_t)i * DD;
            a0 += __half2float(r[tid]);
            a1 += __half2float(r[tid + 256]);
            a2 += __half2float(r[tid + 512]);
        }
        s_in[tid]       = a0 * (1.0f / SS);
        s_in[tid + 256] = a1 * (1.0f / SS);
        s_in[tid + 512] = a2 * (1.0f / SS);
    }
    __syncthreads();
    for (int j = tid; j < DD; j += 256) {
        float a = b1[j];
        for (int d = 0; d < DD; d++) a = fmaf(s_in[d], w1[(size_t)d * DD + j], a);
        s_hid[j] = geluf(a);
    }
    __syncthreads();
    if (tid < EE) {
        float a = b2[tid];
        for (int d = 0; d < DD; d++) a = fmaf(s_hid[d], w2[(size_t)d * EE + tid], a);
        s_logits[tid] = a;
    }
    __syncthreads();
    if (tid == 0) {
        float p[EE];
        float mx = -1e30f;
        for (int e = 0; e < EE; e++) mx = fmaxf(mx, s_logits[e]);
        float sum = 0.0f;
        for (int e = 0; e < EE; e++) { p[e] = expf(s_logits[e] - mx); sum += p[e]; }
        float inv = 1.0f / sum;
        for (int e = 0; e < EE; e++) p[e] *= inv;
        int   idx[KK];
        float val[KK];
        bool used[EE] = {};
        for (int k = 0; k < KK; k++) {
            int best = -1; float bv = -1e30f;
            for (int e = 0; e < EE; e++)
                if (!used[e] && p[e] > bv) { bv = p[e]; best = e; }
            used[best] = true; idx[k] = best; val[k] = bv;
        }
        float m2 = val[0];
        float s2 = 0.0f, tw[KK];
        for (int k = 0; k < KK; k++) { tw[k] = expf(val[k] - m2); s2 += tw[k]; }
        float inv2 = 1.0f / s2;
        for (int e = 0; e < EE; e++) g_wgt[b * EE + e] = 0.0f;
        for (int k = 0; k < KK; k++) g_wgt[b * EE + idx[k]] = tw[k] * inv2;
    }
}

__global__ void final_sum_kernel(const float* __restrict__ b2, float* __restrict__ out)
{
    int i = blockIdx.x * 256 + threadIdx.x;
    int n = (i % (DD / 4)) * 4;
    float4 r = *(const float4*)(g_x2 + (size_t)i * 4);
#pragma unroll
    for (int j = 0; j < 6; j++) {
        float4 p = *(const float4*)(g_part[j] + (size_t)i * 4);
        r.x += p.x; r.y += p.y; r.z += p.z; r.w += p.w;
    }
    float4 bb = *(const float4*)(b2 + n);
    r.x += bb.x; r.y += bb.y; r.z += bb.z; r.w += bb.w;
    *(float4*)(out + (size_t)i * 4) = r;
}

// ---------------- launch ----------------
extern "C" void kernel_launch(void* const* d_in, const int* in_sizes, int n_in,
                              void* d_out, int out_size)
{
    const float* x         = (const float*)d_in[0];
    const float* ln1_g     = (const float*)d_in[1];
    const float* ln1_b     = (const float*)d_in[2];
    const float* qkv_w     = (const float*)d_in[3];
    const float* proj_w    = (const float*)d_in[4];
    const float* proj_b    = (const float*)d_in[5];
    const float* ln2_g     = (const float*)d_in[6];
    const float* ln2_b     = (const float*)d_in[7];
    const float* router_w1 = (const float*)d_in[8];
    const float* router_b1 = (const float*)d_in[9];
    const float* router_w2 = (const float*)d_in[10];
    const float* router_b2 = (const float*)d_in[11];
    const float* exp_w1    = (const float*)d_in[12];
    const float* exp_b1    = (const float*)d_in[13];
    const float* exp_w2    = (const float*)d_in[14];
    const float* exp_b2    = (const float*)d_in[15];
    const float* sh_w1     = (const float*)d_in[16];
    const float* sh_b1     = (const float*)d_in[17];
    const float* sh_w2     = (const float*)d_in[18];
    const float* sh_b2     = (const float*)d_in[19];
    float* out = (float*)d_out;

    static cudaStream_t sW = nullptr, sB = nullptr;
    static cudaEvent_t evF1 = nullptr, evWq = nullptr, evW = nullptr, evWX = nullptr,
                       evF2 = nullptr, evB = nullptr;
    if (!sW) {
        cudaStreamCreateWithFlags(&sW, cudaStreamNonBlocking);
        cudaStreamCreateWithFlags(&sB, cudaStreamNonBlocking);
        cudaEventCreateWithFlags(&evF1, cudaEventDisableTiming);
        cudaEventCreateWithFlags(&evWq, cudaEventDisableTiming);
        cudaEventCreateWithFlags(&evW,  cudaEventDisableTiming);
        cudaEventCreateWithFlags(&evWX, cudaEventDisableTiming);
        cudaEventCreateWithFlags(&evF2, cudaEventDisableTiming);
        cudaEventCreateWithFlags(&evB,  cudaEventDisableTiming);
    }

    cudaFuncSetAttribute(qkv_g2,        cudaFuncAttributeMaxDynamicSharedMemorySize, SMEMB_G2);
    cudaFuncSetAttribute(proj_g2,       cudaFuncAttributeMaxDynamicSharedMemorySize, SMEMB_G2);
    cudaFuncSetAttribute(expert_hid_g2, cudaFuncAttributeMaxDynamicSharedMemorySize, SMEMB_G2);
    cudaFuncSetAttribute(expert_out_g2, cudaFuncAttributeMaxDynamicSharedMemorySize, SMEMB_G2);
    cudaFuncSetAttribute(shared_hid_g2, cudaFuncAttributeMaxDynamicSharedMemorySize, SMEMB_G2);
    cudaFuncSetAttribute(final_split_g2,cudaFuncAttributeMaxDynamicSharedMemorySize, SMEMB_G2);
    cudaFuncSetAttribute(flash_tc,      cudaFuncAttributeMaxDynamicSharedMemorySize, FLASH_SMEM);

    __half* wq;  cudaGetSymbolAddress((void**)&wq,  g_qkvw_h);
    __half* wp;  cudaGetSymbolAddress((void**)&wp,  g_projw_h);
    __half* w1;  cudaGetSymbolAddress((void**)&w1,  g_shw1_h);
    __half* w2;  cudaGetSymbolAddress((void**)&w2,  g_shw2_h);
    __half* h1h; cudaGetSymbolAddress((void**)&h1h, g_h1h);
    __half* h2h; cudaGetSymbolAddress((void**)&h2h, g_h2h);
    float*  x2;  cudaGetSymbolAddress((void**)&x2,  g_x2);

    // fork sW: qkv weight FIRST (unblocks the first GEMM asap), then the rest
    cudaEventRecord(evF1, 0);
    cudaStreamWaitEvent(sW, evF1, 0);
    f2h_kernel<<<(DD*3*DD/8 + 255)/256, 256, 0, sW>>>(qkv_w, wq, DD*3*DD/8);
    cudaEventRecord(evWq, sW);
    f2h_kernel<<<(DD*DD/8   + 255)/256, 256, 0, sW>>>(proj_w, wp, DD*DD/8);
    f2h_kernel<<<(DD*SHH/8  + 255)/256, 256, 0, sW>>>(sh_w1, w1, DD*SHH/8);
    f2h_kernel<<<(SHH*DD/8  + 255)/256, 256, 0, sW>>>(sh_w2, w2, SHH*DD/8);
    cudaEventRecord(evW, sW);
    expconv_kernel<<<dim3(2*DD*HID/8/256, EE), 256, 0, sW>>>(exp_w1, exp_w2);
    cudaEventRecord(evWX, sW);

    // attention branch (main stream)
    ln_kernel<<<NTOK, 256>>>(x, ln1_g, ln1_b, h1h);
    cudaStreamWaitEvent(0, evWq, 0);
    qkv_g2<<<dim3(18, 32), 128, SMEMB_G2>>>();
    flash_tc<<<dim3(4, BHN), 256, FLASH_SMEM>>>();
    cudaStreamWaitEvent(0, evW, 0);
    proj_g2<<<dim3(6, 32), 128, SMEMB_G2>>>(proj_b, x);

    // ln2 -> fork shared-expert chain onto sB
    ln_kernel<<<NTOK, 256>>>(x2, ln2_g, ln2_b, h2h);
    cudaEventRecord(evF2, 0);
    cudaStreamWaitEvent(sB, evF2, 0);
    cudaStreamWaitEvent(sB, evW, 0);
    shared_hid_g2<<<dim3(24, 32), 128, SMEMB_G2, sB>>>(sh_b1);
    final_split_g2<<<dim3(6, 32, 2), 128, SMEMB_G2, sB>>>();
    cudaEventRecord(evB, sB);

    // routed-expert chain (main stream, overlaps sB)
    router_kernel<<<BB, 256>>>(router_w1, router_b1, router_w2, router_b2);
    cudaStreamWaitEvent(0, evWX, 0);
    expert_hid_g2<<<dim3(12, 4, BB * KK), 128, SMEMB_G2>>>(exp_b1);
    expert_out_g2<<<dim3(6, 4, BB * KK), 128, SMEMB_G2>>>(exp_b2);

    // join and reduce
    cudaStreamWaitEvent(0, evB, 0);
    final_sum_kernel<<<NTOK * DD / 4 / 256, 256>>>(sh_b2, out);
}

// round 16
// speedup vs baseline: 1.3325x; 1.1502x over previous
#include <cuda_runtime.h>
#include <cuda_fp16.h>
#include <cstdint>
#include <math.h>

// ---------------- problem constants ----------------
#define BB   8
#define SS   512
#define DD   768
#define HH   12
#define DH   64
#define EE   14
#define KK   4
#define HID  1536
#define SHH  3072
#define NTOK (BB*SS)          // 4096
#define BHN  (BB*HH)          // 96

// ---------------- scratch (device globals; no allocation) ----------------
__device__ __align__(128) __half g_h1h [(size_t)NTOK*DD];
__device__ __align__(128) __half g_qh  [(size_t)BHN*SS*DH];
__device__ __align__(128) __half g_kh  [(size_t)BHN*SS*DH];
__device__ __align__(128) __half g_vh  [(size_t)BHN*SS*DH];
__device__ __align__(128) __half g_aoh [(size_t)NTOK*DD];
__device__ __align__(128) float  g_x2  [(size_t)NTOK*DD];
__device__ __align__(128) __half g_h2h [(size_t)NTOK*DD];
__device__ __align__(128) float  g_wgt [(size_t)BB*EE];
__device__ __align__(128) __half g_ehidh[(size_t)EE*BB*SS*HID];
__device__ __align__(128) __half g_shidh[(size_t)NTOK*SHH];
__device__ __align__(128) float  g_part[6][(size_t)NTOK*DD];   // 0..3 expert slots, 4..5 final
// fp16 weight mirrors, [K][N] row-major
__device__ __align__(128) __half g_qkvw_h [(size_t)DD*3*DD];
__device__ __align__(128) __half g_projw_h[(size_t)DD*DD];
__device__ __align__(128) __half g_shw1_h [(size_t)DD*SHH];
__device__ __align__(128) __half g_shw2_h [(size_t)SHH*DD];
__device__ __align__(128) __half g_expw1_h[(size_t)EE*DD*HID];
__device__ __align__(128) __half g_expw2_h[(size_t)EE*HID*DD];

// ---------------- helpers ----------------
__device__ __forceinline__ float geluf(float x) {
    return 0.5f * x * (1.0f + erff(x * 0.70710678118654752f));
}
__device__ __forceinline__ uint32_t packh2(float a, float b) {
    __half2 h = __floats2half2_rn(a, b);
    return *(uint32_t*)&h;
}
__device__ __forceinline__ void cp16h(__half* dst_smem, const __half* src) {
    uint32_t d = (uint32_t)__cvta_generic_to_shared(dst_smem);
    asm volatile("cp.async.cg.shared.global [%0], [%1], 16;" :: "r"(d), "l"(src));
}
__device__ __forceinline__ void ldsm4(uint32_t &r0, uint32_t &r1, uint32_t &r2, uint32_t &r3,
                                      uint32_t addr) {
    asm volatile("ldmatrix.sync.aligned.m8n8.x4.shared.b16 {%0,%1,%2,%3}, [%4];"
                 : "=r"(r0), "=r"(r1), "=r"(r2), "=r"(r3) : "r"(addr));
}
__device__ __forceinline__ void ldsm4t(uint32_t &r0, uint32_t &r1, uint32_t &r2, uint32_t &r3,
                                       uint32_t addr) {
    asm volatile("ldmatrix.sync.aligned.m8n8.x4.trans.shared.b16 {%0,%1,%2,%3}, [%4];"
                 : "=r"(r0), "=r"(r1), "=r"(r2), "=r"(r3) : "r"(addr));
}
__device__ __forceinline__ void mma_f16(float c[4], const uint32_t a[4], const uint32_t b[2]) {
    asm volatile("mma.sync.aligned.m16n8k16.row.col.f32.f16.f16.f32 "
                 "{%0,%1,%2,%3}, {%4,%5,%6,%7}, {%8,%9}, {%0,%1,%2,%3};"
                 : "+f"(c[0]), "+f"(c[1]), "+f"(c[2]), "+f"(c[3])
                 : "r"(a[0]), "r"(a[1]), "r"(a[2]), "r"(a[3]), "r"(b[0]), "r"(b[1]));
}

__device__ __forceinline__ float blockReduceSum(float v, float* sh) {
    int tid = threadIdx.x;
    sh[tid] = v; __syncthreads();
    for (int s = 128; s > 0; s >>= 1) {
        if (tid < s) sh[tid] += sh[tid + s];
        __syncthreads();
    }
    float r = sh[0]; __syncthreads();
    return r;
}

// ======================================================================
// fp16 GEMM core: 128 threads / 4 warps, warp tile 64x64, CTA 128x128,
// BK=64, 3-stage cp.async, one barrier per 64 k-elements, register
// double-buffered fragments.
// ======================================================================
#define G2_LDA 72
#define G2_LDB 136
#define G2_ASZ (128*G2_LDA)
#define G2_BSZ (64*G2_LDB)
#define G2_STG (G2_ASZ + G2_BSZ)          // 17920 halves = 35840 B
#define SMEMB_G2 (3 * G2_STG * 2)         // 107520 B

__device__ __forceinline__ void gemm2(const __half* __restrict__ A, int lda,
                                      const __half* __restrict__ B, int ldb,
                                      int K, __half* smem, float acc[4][8][4])
{
    const int tid  = threadIdx.x;         // 128
    const int lane = tid & 31;
    const int w    = tid >> 5;
    const int wm   = w >> 1;
    const int wn   = w & 1;
    const int l16  = lane & 15;
    const int lh   = lane >> 4;

#define G2_LOAD(kt, stg)                                                     \
    { __half* bA = smem + (stg) * G2_STG;                                    \
      __half* bBp = bA + G2_ASZ;                                             \
      _Pragma("unroll")                                                      \
      for (int i = 0; i < 8; i++) {                                          \
          int e = tid + i * 128; int row = e >> 3, v = e & 7;                \
          cp16h(bA + row * G2_LDA + v * 8, A + (size_t)row * lda + (kt) + v * 8); } \
      _Pragma("unroll")                                                      \
      for (int i = 0; i < 8; i++) {                                          \
          int e = tid + i * 128; int row = e >> 4, v = e & 15;               \
          cp16h(bBp + row * G2_LDB + v * 8, B + (size_t)((kt) + row) * ldb + v * 8); } }

#define G2_FRAG(kk, buf, aB, bBa)                                            \
    { int k0 = (kk) * 16;                                                    \
      _Pragma("unroll")                                                      \
      for (int mt = 0; mt < 4; mt++)                                         \
          ldsm4(a[buf][mt][0], a[buf][mt][1], a[buf][mt][2], a[buf][mt][3],  \
                (aB) + 2u * ((wm * 64 + mt * 16 + l16) * G2_LDA + k0 + lh * 8)); \
      _Pragma("unroll")                                                      \
      for (int p = 0; p < 4; p++) {                                          \
          uint32_t r0, r1, r2, r3;                                           \
          ldsm4t(r0, r1, r2, r3,                                             \
                 (bBa) + 2u * ((k0 + l16) * G2_LDB + wn * 64 + p * 16 + lh * 8)); \
          b[buf][2 * p][0] = r0; b[buf][2 * p][1] = r1;                      \
          b[buf][2 * p + 1][0] = r2; b[buf][2 * p + 1][1] = r3; } }

    const int nst = K / 64;
    G2_LOAD(0, 0);
    asm volatile("cp.async.commit_group;");
    G2_LOAD(64, 1);
    asm volatile("cp.async.commit_group;");

    uint32_t a[2][4][4], b[2][8][2];

    int stg = 0;
    for (int t = 0; t < nst; t++) {
        if (t + 1 < nst) asm volatile("cp.async.wait_group 1;" ::: "memory");
        else             asm volatile("cp.async.wait_group 0;" ::: "memory");
        __syncthreads();
        if (t + 2 < nst) {
            int ns = stg + 2; if (ns >= 3) ns -= 3;
            G2_LOAD((t + 2) * 64, ns);
            asm volatile("cp.async.commit_group;");
        }
        __half* cA = smem + stg * G2_STG;
        uint32_t aB = (uint32_t)__cvta_generic_to_shared(cA);
        uint32_t bBa = (uint32_t)__cvta_generic_to_shared(cA + G2_ASZ);

        G2_FRAG(0, 0, aB, bBa);
#pragma unroll
        for (int kk = 0; kk < 4; kk++) {
            if (kk < 3) G2_FRAG(kk + 1, (kk + 1) & 1, aB, bBa);
#pragma unroll
            for (int mt = 0; mt < 4; mt++)
#pragma unroll
                for (int nt = 0; nt < 8; nt++)
                    mma_f16(acc[mt][nt], a[kk & 1][mt], b[kk & 1][nt]);
        }
        if (++stg == 3) stg = 0;
    }
#undef G2_LOAD
#undef G2_FRAG
}

#define EPI2_SETUP()                                            \
    const int tid = threadIdx.x;                                \
    const int lane = tid & 31, w = tid >> 5;                    \
    const int wm = w >> 1, wn = w & 1;                          \
    const int g = lane >> 2, tig = lane & 3;

// ---------------- gemm2 kernels (128 threads each) ----------------

__global__ void __launch_bounds__(128) qkv_g2()
{
    extern __shared__ __half smem[];
    int row0 = blockIdx.y * 128, col0 = blockIdx.x * 128;
    float acc[4][8][4] = {};
    gemm2(g_h1h + (size_t)row0 * DD, DD, g_qkvw_h + col0, 3 * DD, DD, smem, acc);
    EPI2_SETUP();
#pragma unroll
    for (int mt = 0; mt < 4; mt++)
#pragma unroll
        for (int nt = 0; nt < 8; nt++) {
            int n = col0 + wn * 64 + nt * 8 + 2 * tig;
            int which = n / DD;
            int rem = n - which * DD;
            int h = rem >> 6, d = rem & 63;
            __half* dst = (which == 0) ? g_qh : ((which == 1) ? g_kh : g_vh);
#pragma unroll
            for (int hf = 0; hf < 2; hf++) {
                int m = row0 + wm * 64 + mt * 16 + g + hf * 8;
                int b = m >> 9, s = m & 511;
                *(__half2*)&dst[(((size_t)b * HH + h) * SS + s) * DH + d] =
                    __floats2half2_rn(acc[mt][nt][2 * hf], acc[mt][nt][2 * hf + 1]);
            }
        }
}

__global__ void __launch_bounds__(128) proj_g2(const float* __restrict__ bias,
                                               const float* __restrict__ x)
{
    extern __shared__ __half smem[];
    int row0 = blockIdx.y * 128, col0 = blockIdx.x * 128;
    float acc[4][8][4] = {};
    gemm2(g_aoh + (size_t)row0 * DD, DD, g_projw_h + col0, DD, DD, smem, acc);
    EPI2_SETUP();
#pragma unroll
    for (int mt = 0; mt < 4; mt++)
#pragma unroll
        for (int nt = 0; nt < 8; nt++) {
            int n = col0 + wn * 64 + nt * 8 + 2 * tig;
            float b0 = bias[n], b1 = bias[n + 1];
#pragma unroll
            for (int hf = 0; hf < 2; hf++) {
                int m = row0 + wm * 64 + mt * 16 + g + hf * 8;
                size_t idx = (size_t)m * DD + n;
                float2 xv = *(const float2*)&x[idx];
                *(float2*)&g_x2[idx] =
                    make_float2(xv.x + acc[mt][nt][2 * hf] + b0,
                                xv.y + acc[mt][nt][2 * hf + 1] + b1);
            }
        }
}

// expert hidden, slot-parallel (z = b*KK + slot, 32 slices, all active)
__global__ void __launch_bounds__(128) expert_hid_g2(const float* __restrict__ b1)
{
    extern __shared__ __half smem[];
    int b = blockIdx.z >> 2, slot = blockIdx.z & 3;
    int e = 0; float wv = 0.0f;
    {
        int cnt = -1;
        for (int j = 0; j < EE; j++) {
            float t = g_wgt[b * EE + j];
            if (t != 0.0f) { cnt++; if (cnt == slot) { e = j; wv = t; break; } }
        }
    }
    int row0 = blockIdx.y * 128, col0 = blockIdx.x * 128;
    float acc[4][8][4] = {};
    gemm2(g_h2h + ((size_t)b * SS + row0) * DD, DD,
          g_expw1_h + (size_t)e * DD * HID + col0, HID, DD, smem, acc);
    EPI2_SETUP();
    __half* dst = g_ehidh + ((size_t)e * BB + b) * SS * HID;
#pragma unroll
    for (int mt = 0; mt < 4; mt++)
#pragma unroll
        for (int nt = 0; nt < 8; nt++) {
            int n = col0 + wn * 64 + nt * 8 + 2 * tig;
            float b0 = b1[e * HID + n], bx = b1[e * HID + n + 1];
#pragma unroll
            for (int hf = 0; hf < 2; hf++) {
                int m = row0 + wm * 64 + mt * 16 + g + hf * 8;
                *(__half2*)&dst[(size_t)m * HID + n] =
                    __floats2half2_rn(wv * geluf(acc[mt][nt][2 * hf] + b0),
                                      wv * geluf(acc[mt][nt][2 * hf + 1] + bx));
            }
        }
}

// expert out, slot-parallel: one block set per (b, slot) -> g_part[slot]
__global__ void __launch_bounds__(128) expert_out_g2(const float* __restrict__ b2)
{
    extern __shared__ __half smem[];
    int b = blockIdx.z >> 2, slot = blockIdx.z & 3;
    int e = 0; float wv = 0.0f;
    {
        int cnt = -1;
        for (int j = 0; j < EE; j++) {
            float t = g_wgt[b * EE + j];
            if (t != 0.0f) { cnt++; if (cnt == slot) { e = j; wv = t; break; } }
        }
    }
    int row0 = blockIdx.y * 128, col0 = blockIdx.x * 128;
    float acc[4][8][4] = {};
    gemm2(g_ehidh + (((size_t)e * BB + b) * SS + row0) * HID, HID,
          g_expw2_h + (size_t)e * HID * DD + col0, DD, HID, smem, acc);
    EPI2_SETUP();
    float* dst = g_part[slot];
#pragma unroll
    for (int mt = 0; mt < 4; mt++)
#pragma unroll
        for (int nt = 0; nt < 8; nt++) {
            int n = col0 + wn * 64 + nt * 8 + 2 * tig;
            float b0 = wv * b2[e * DD + n], b1v = wv * b2[e * DD + n + 1];
#pragma unroll
            for (int hf = 0; hf < 2; hf++) {
                int m = row0 + wm * 64 + mt * 16 + g + hf * 8;
                *(float2*)&dst[((size_t)b * SS + m) * DD + n] =
                    make_float2(acc[mt][nt][2 * hf] + b0,
                                acc[mt][nt][2 * hf + 1] + b1v);
            }
        }
}

__global__ void __launch_bounds__(128) shared_hid_g2(const float* __restrict__ b1)
{
    extern __shared__ __half smem[];
    int row0 = blockIdx.y * 128, col0 = blockIdx.x * 128;
    float acc[4][8][4] = {};
    gemm2(g_h2h + (size_t)row0 * DD, DD, g_shw1_h + col0, SHH, DD, smem, acc);
    EPI2_SETUP();
#pragma unroll
    for (int mt = 0; mt < 4; mt++)
#pragma unroll
        for (int nt = 0; nt < 8; nt++) {
            int n = col0 + wn * 64 + nt * 8 + 2 * tig;
            float b0 = b1[n], bx = b1[n + 1];
#pragma unroll
            for (int hf = 0; hf < 2; hf++) {
                int m = row0 + wm * 64 + mt * 16 + g + hf * 8;
                *(__half2*)&g_shidh[(size_t)m * SHH + n] =
                    __floats2half2_rn(geluf(acc[mt][nt][2 * hf] + b0),
                                      geluf(acc[mt][nt][2 * hf + 1] + bx));
            }
        }
}

// final split-K chunk c (2 chunks of K=1536): g_part[4+c]
__global__ void __launch_bounds__(128) final_split_g2()
{
    extern __shared__ __half smem[];
    int c = blockIdx.z;
    int row0 = blockIdx.y * 128, col0 = blockIdx.x * 128;
    float acc[4][8][4] = {};
    gemm2(g_shidh + (size_t)row0 * SHH + c * 1536, SHH,
          g_shw2_h + (size_t)(c * 1536) * DD + col0, DD, 1536, smem, acc);
    EPI2_SETUP();
    float* dst = g_part[4 + c];
#pragma unroll
    for (int mt = 0; mt < 4; mt++)
#pragma unroll
        for (int nt = 0; nt < 8; nt++) {
            int n = col0 + wn * 64 + nt * 8 + 2 * tig;
#pragma unroll
            for (int hf = 0; hf < 2; hf++) {
                int m = row0 + wm * 64 + mt * 16 + g + hf * 8;
                *(float2*)&dst[(size_t)m * DD + n] =
                    make_float2(acc[mt][nt][2 * hf], acc[mt][nt][2 * hf + 1]);
            }
        }
}

// ---------------- flash attention (fp16, P in registers) ----------------
#define FLDA 72
#define FLASH_SMEM (3 * 128 * FLDA * 2)

__global__ void __launch_bounds__(256, 1) flash_tc()
{
    extern __shared__ __half hsm[];
    __half* sQ = hsm;
    __half* sK = hsm + 128 * FLDA;
    __half* sV = hsm + 2 * 128 * FLDA;

    const int bh = blockIdx.y;
    const int q0 = blockIdx.x * 128;
    const __half* Qg = g_qh + ((size_t)bh * SS + q0) * DH;
    const __half* Kg = g_kh + (size_t)bh * SS * DH;
    const __half* Vg = g_vh + (size_t)bh * SS * DH;

    const int tid = threadIdx.x, lane = tid & 31, w = tid >> 5;
    const int l16 = lane & 15, lh = lane >> 4;
    const int g = lane >> 2, tig = lane & 3;

#define FCOPY(dst, src)                                                       \
    { _Pragma("unroll")                                                       \
      for (int i = 0; i < 4; i++) {                                           \
          int e = tid + i * 256; int r = e >> 3, v = e & 7;                   \
          cp16h((dst) + r * FLDA + v * 8, (src) + (size_t)r * 64 + v * 8); } }

    FCOPY(sQ, Qg);
    FCOPY(sK, Kg);
    asm volatile("cp.async.commit_group;");
    FCOPY(sV, Vg);
    asm volatile("cp.async.commit_group;");

    float acc_o[8][4] = {};
    float mrun[2] = {-1e30f, -1e30f};
    float lrun[2] = {0.0f, 0.0f};

    const uint32_t sQa = (uint32_t)__cvta_generic_to_shared(sQ);
    const uint32_t sKa = (uint32_t)__cvta_generic_to_shared(sK);
    const uint32_t sVa = (uint32_t)__cvta_generic_to_shared(sV);

    for (int st = 0; st < 4; st++) {
        asm volatile("cp.async.wait_group 1;" ::: "memory");
        __syncthreads();

        float s[16][4] = {};
#pragma unroll
        for (int kk = 0; kk < 4; kk++) {
            int k0 = kk * 16;
            uint32_t a[4];
            ldsm4(a[0], a[1], a[2], a[3],
                  sQa + 2u * ((w * 16 + l16) * FLDA + k0 + lh * 8));
#pragma unroll
            for (int p = 0; p < 8; p++) {
                uint32_t r0, r1, r2, r3;
                ldsm4(r0, r1, r2, r3,
                      sKa + 2u * ((p * 16 + l16) * FLDA + k0 + lh * 8));
                uint32_t b0[2] = {r0, r2}, b1[2] = {r1, r3};
                mma_f16(s[2 * p], a, b0);
                mma_f16(s[2 * p + 1], a, b1);
            }
        }

        float tmax[2] = {-1e30f, -1e30f};
#pragma unroll
        for (int nt = 0; nt < 16; nt++) {
            tmax[0] = fmaxf(tmax[0], fmaxf(s[nt][0], s[nt][1]));
            tmax[1] = fmaxf(tmax[1], fmaxf(s[nt][2], s[nt][3]));
        }
#pragma unroll
        for (int o = 1; o < 4; o <<= 1) {
            tmax[0] = fmaxf(tmax[0], __shfl_xor_sync(0xffffffffu, tmax[0], o));
            tmax[1] = fmaxf(tmax[1], __shfl_xor_sync(0xffffffffu, tmax[1], o));
        }
        float mnew[2], corr[2], rsum[2] = {0.0f, 0.0f};
#pragma unroll
        for (int h = 0; h < 2; h++) {
            mnew[h] = fmaxf(mrun[h], tmax[h] * 0.125f);
            corr[h] = __expf(mrun[h] - mnew[h]);
            mrun[h] = mnew[h];
        }
        uint32_t ph[16][2];
#pragma unroll
        for (int nt = 0; nt < 16; nt++) {
            float p0 = __expf(s[nt][0] * 0.125f - mnew[0]);
            float p1 = __expf(s[nt][1] * 0.125f - mnew[0]);
            float p2 = __expf(s[nt][2] * 0.125f - mnew[1]);
            float p3 = __expf(s[nt][3] * 0.125f - mnew[1]);
            rsum[0] += p0 + p1; rsum[1] += p2 + p3;
            ph[nt][0] = packh2(p0, p1);
            ph[nt][1] = packh2(p2, p3);
        }
#pragma unroll
        for (int o = 1; o < 4; o <<= 1) {
            rsum[0] += __shfl_xor_sync(0xffffffffu, rsum[0], o);
            rsum[1] += __shfl_xor_sync(0xffffffffu, rsum[1], o);
        }
        lrun[0] = lrun[0] * corr[0] + rsum[0];
        lrun[1] = lrun[1] * corr[1] + rsum[1];
#pragma unroll
        for (int nt = 0; nt < 8; nt++) {
            acc_o[nt][0] *= corr[0]; acc_o[nt][1] *= corr[0];
            acc_o[nt][2] *= corr[1]; acc_o[nt][3] *= corr[1];
        }

        asm volatile("cp.async.wait_group 0;" ::: "memory");
        __syncthreads();
        if (st < 3) {
            FCOPY(sK, Kg + (size_t)(st + 1) * 128 * 64);
            asm volatile("cp.async.commit_group;");
        }

#pragma unroll
        for (int j = 0; j < 8; j++) {
            int k0 = j * 16;
            uint32_t a[4] = {ph[2 * j][0], ph[2 * j][1], ph[2 * j + 1][0], ph[2 * j + 1][1]};
#pragma unroll
            for (int p = 0; p < 4; p++) {
                uint32_t r0, r1, r2, r3;
                ldsm4t(r0, r1, r2, r3,
                       sVa + 2u * ((k0 + l16) * FLDA + p * 16 + lh * 8));
                uint32_t b0[2] = {r0, r1}, b1[2] = {r2, r3};
                mma_f16(acc_o[2 * p], a, b0);
                mma_f16(acc_o[2 * p + 1], a, b1);
            }
        }
        __syncthreads();
        if (st < 3) {
            FCOPY(sV, Vg + (size_t)(st + 1) * 128 * 64);
            asm volatile("cp.async.commit_group;");
        }
    }

    const int b = bh / HH, hh = bh - b * HH;
    const float inv0 = 1.0f / lrun[0], inv1 = 1.0f / lrun[1];
    const int m0 = q0 + w * 16 + g;
#pragma unroll
    for (int nt = 0; nt < 8; nt++) {
        int d = nt * 8 + 2 * tig;
        *(__half2*)&g_aoh[((size_t)b * SS + m0) * DD + hh * DH + d] =
            __floats2half2_rn(acc_o[nt][0] * inv0, acc_o[nt][1] * inv0);
        *(__half2*)&g_aoh[((size_t)b * SS + m0 + 8) * DD + hh * DH + d] =
            __floats2half2_rn(acc_o[nt][2] * inv1, acc_o[nt][3] * inv1);
    }
#undef FCOPY
}

// ---------------- conversion kernels ----------------
__global__ void f2h_kernel(const float* __restrict__ in, __half* __restrict__ out, int n8)
{
    int i = blockIdx.x * 256 + threadIdx.x;
    if (i >= n8) return;
    float4 a = ((const float4*)in)[2 * i];
    float4 b = ((const float4*)in)[2 * i + 1];
    uint4 u;
    u.x = packh2(a.x, a.y); u.y = packh2(a.z, a.w);
    u.z = packh2(b.x, b.y); u.w = packh2(b.z, b.w);
    ((uint4*)out)[i] = u;
}

__global__ void expconv_kernel(const float* __restrict__ w1, const float* __restrict__ w2)
{
    int e = blockIdx.y;
    int i = blockIdx.x * 256 + threadIdx.x;
    const int n8 = DD * HID / 8;
    const float* src; __half* dst; int j;
    if (i < n8) { src = w1 + (size_t)e * DD * HID; dst = g_expw1_h + (size_t)e * DD * HID; j = i; }
    else        { src = w2 + (size_t)e * HID * DD; dst = g_expw2_h + (size_t)e * HID * DD; j = i - n8; }
    float4 a = ((const float4*)src)[2 * j];
    float4 b = ((const float4*)src)[2 * j + 1];
    uint4 u;
    u.x = packh2(a.x, a.y); u.y = packh2(a.z, a.w);
    u.z = packh2(b.x, b.y); u.w = packh2(b.z, b.w);
    ((uint4*)dst)[j] = u;
}

// ---------------- elementwise kernels ----------------
__global__ void ln_kernel(const float* __restrict__ in, const float* __restrict__ g,
                          const float* __restrict__ b, __half* __restrict__ outh)
{
    __shared__ float red[256];
    size_t row = blockIdx.x;
    const float* xr = in + row * DD;
    int tid = threadIdx.x;
    float x0 = xr[tid], x1 = xr[tid + 256], x2 = xr[tid + 512];
    float total = blockReduceSum(x0 + x1 + x2, red);
    float mean = total * (1.0f / DD);
    float d0 = x0 - mean, d1 = x1 - mean, d2 = x2 - mean;
    float var = blockReduceSum(d0 * d0 + d1 * d1 + d2 * d2, red) * (1.0f / DD);
    float rstd = rsqrtf(var + 1e-5f);
    outh[row * DD + tid]       = __float2half_rn(d0 * rstd * g[tid]       + b[tid]);
    outh[row * DD + tid + 256] = __float2half_rn(d1 * rstd * g[tid + 256] + b[tid + 256]);
    outh[row * DD + tid + 512] = __float2half_rn(d2 * rstd * g[tid + 512] + b[tid + 512]);
}

// fused seq-mean + router MLP + top-4; 1024 threads, one block per batch.
// Mean phase: 4 row-groups x 256 threads (128 rows each), smem reduction.
__global__ void __launch_bounds__(1024) router_kernel(
    const float* __restrict__ w1, const float* __restrict__ b1,
    const float* __restrict__ w2, const float* __restrict__ b2)
{
    __shared__ float sred[4][DD];
    __shared__ float s_in[DD];
    __shared__ float s_hid[DD];
    __shared__ float s_logits[EE];
    int b = blockIdx.x;
    int tid = threadIdx.x;
    int grp = tid >> 8;          // 0..3
    int t   = tid & 255;
    {
        const __half* base = g_h2h + (size_t)b * SS * DD + (size_t)(grp * 128) * DD;
        float a0 = 0.0f, a1 = 0.0f, a2 = 0.0f;
#pragma unroll 4
        for (int i = 0; i < 128; i++) {
            const __half* r = base + (size_t)i * DD;
            a0 += __half2float(r[t]);
            a1 += __half2float(r[t + 256]);
            a2 += __half2float(r[t + 512]);
        }
        sred[grp][t]       = a0;
        sred[grp][t + 256] = a1;
        sred[grp][t + 512] = a2;
    }
    __syncthreads();
    if (tid < DD)
        s_in[tid] = (sred[0][tid] + sred[1][tid] + sred[2][tid] + sred[3][tid]) * (1.0f / SS);
    __syncthreads();
    if (tid < DD) {
        // 4 partial accumulators for FMA ILP
        float p0 = 0.0f, p1 = 0.0f, p2 = 0.0f, p3 = 0.0f;
#pragma unroll 4
        for (int d = 0; d < DD; d += 4) {
            p0 = fmaf(s_in[d],     w1[(size_t)d * DD + tid],       p0);
            p1 = fmaf(s_in[d + 1], w1[(size_t)(d + 1) * DD + tid], p1);
            p2 = fmaf(s_in[d + 2], w1[(size_t)(d + 2) * DD + tid], p2);
            p3 = fmaf(s_in[d + 3], w1[(size_t)(d + 3) * DD + tid], p3);
        }
        s_hid[tid] = geluf(b1[tid] + ((p0 + p1) + (p2 + p3)));
    }
    __syncthreads();
    if (tid < EE) {
        float a = b2[tid];
        for (int d = 0; d < DD; d++) a = fmaf(s_hid[d], w2[(size_t)d * EE + tid], a);
        s_logits[tid] = a;
    }
    __syncthreads();
    if (tid == 0) {
        float p[EE];
        float mx = -1e30f;
        for (int e = 0; e < EE; e++) mx = fmaxf(mx, s_logits[e]);
        float sum = 0.0f;
        for (int e = 0; e < EE; e++) { p[e] = expf(s_logits[e] - mx); sum += p[e]; }
        float inv = 1.0f / sum;
        for (int e = 0; e < EE; e++) p[e] *= inv;
        int   idx[KK];
        float val[KK];
        bool used[EE] = {};
        for (int k = 0; k < KK; k++) {
            int best = -1; float bv = -1e30f;
            for (int e = 0; e < EE; e++)
                if (!used[e] && p[e] > bv) { bv = p[e]; best = e; }
            used[best] = true; idx[k] = best; val[k] = bv;
        }
        float m2 = val[0];
        float s2 = 0.0f, tw[KK];
        for (int k = 0; k < KK; k++) { tw[k] = expf(val[k] - m2); s2 += tw[k]; }
        float inv2 = 1.0f / s2;
        for (int e = 0; e < EE; e++) g_wgt[b * EE + e] = 0.0f;
        for (int k = 0; k < KK; k++) g_wgt[b * EE + idx[k]] = tw[k] * inv2;
    }
}

__global__ void final_sum_kernel(const float* __restrict__ b2, float* __restrict__ out)
{
    int i = blockIdx.x * 256 + threadIdx.x;
    int n = (i % (DD / 4)) * 4;
    float4 r = *(const float4*)(g_x2 + (size_t)i * 4);
#pragma unroll
    for (int j = 0; j < 6; j++) {
        float4 p = *(const float4*)(g_part[j] + (size_t)i * 4);
        r.x += p.x; r.y += p.y; r.z += p.z; r.w += p.w;
    }
    float4 bb = *(const float4*)(b2 + n);
    r.x += bb.x; r.y += bb.y; r.z += bb.z; r.w += bb.w;
    *(float4*)(out + (size_t)i * 4) = r;
}

// ---------------- launch ----------------
extern "C" void kernel_launch(void* const* d_in, const int* in_sizes, int n_in,
                              void* d_out, int out_size)
{
    const float* x         = (const float*)d_in[0];
    const float* ln1_g     = (const float*)d_in[1];
    const float* ln1_b     = (const float*)d_in[2];
    const float* qkv_w     = (const float*)d_in[3];
    const float* proj_w    = (const float*)d_in[4];
    const float* proj_b    = (const float*)d_in[5];
    const float* ln2_g     = (const float*)d_in[6];
    const float* ln2_b     = (const float*)d_in[7];
    const float* router_w1 = (const float*)d_in[8];
    const float* router_b1 = (const float*)d_in[9];
    const float* router_w2 = (const float*)d_in[10];
    const float* router_b2 = (const float*)d_in[11];
    const float* exp_w1    = (const float*)d_in[12];
    const float* exp_b1    = (const float*)d_in[13];
    const float* exp_w2    = (const float*)d_in[14];
    const float* exp_b2    = (const float*)d_in[15];
    const float* sh_w1     = (const float*)d_in[16];
    const float* sh_b1     = (const float*)d_in[17];
    const float* sh_w2     = (const float*)d_in[18];
    const float* sh_b2     = (const float*)d_in[19];
    float* out = (float*)d_out;

    static cudaStream_t sW = nullptr, sB = nullptr;
    static cudaEvent_t evF1 = nullptr, evWq = nullptr, evW = nullptr, evWX = nullptr,
                       evF2 = nullptr, evB = nullptr;
    if (!sW) {
        cudaStreamCreateWithFlags(&sW, cudaStreamNonBlocking);
        cudaStreamCreateWithFlags(&sB, cudaStreamNonBlocking);
        cudaEventCreateWithFlags(&evF1, cudaEventDisableTiming);
        cudaEventCreateWithFlags(&evWq, cudaEventDisableTiming);
        cudaEventCreateWithFlags(&evW,  cudaEventDisableTiming);
        cudaEventCreateWithFlags(&evWX, cudaEventDisableTiming);
        cudaEventCreateWithFlags(&evF2, cudaEventDisableTiming);
        cudaEventCreateWithFlags(&evB,  cudaEventDisableTiming);
    }

    cudaFuncSetAttribute(qkv_g2,        cudaFuncAttributeMaxDynamicSharedMemorySize, SMEMB_G2);
    cudaFuncSetAttribute(proj_g2,       cudaFuncAttributeMaxDynamicSharedMemorySize, SMEMB_G2);
    cudaFuncSetAttribute(expert_hid_g2, cudaFuncAttributeMaxDynamicSharedMemorySize, SMEMB_G2);
    cudaFuncSetAttribute(expert_out_g2, cudaFuncAttributeMaxDynamicSharedMemorySize, SMEMB_G2);
    cudaFuncSetAttribute(shared_hid_g2, cudaFuncAttributeMaxDynamicSharedMemorySize, SMEMB_G2);
    cudaFuncSetAttribute(final_split_g2,cudaFuncAttributeMaxDynamicSharedMemorySize, SMEMB_G2);
    cudaFuncSetAttribute(flash_tc,      cudaFuncAttributeMaxDynamicSharedMemorySize, FLASH_SMEM);

    __half* wq;  cudaGetSymbolAddress((void**)&wq,  g_qkvw_h);
    __half* wp;  cudaGetSymbolAddress((void**)&wp,  g_projw_h);
    __half* w1;  cudaGetSymbolAddress((void**)&w1,  g_shw1_h);
    __half* w2;  cudaGetSymbolAddress((void**)&w2,  g_shw2_h);
    __half* h1h; cudaGetSymbolAddress((void**)&h1h, g_h1h);
    __half* h2h; cudaGetSymbolAddress((void**)&h2h, g_h2h);
    float*  x2;  cudaGetSymbolAddress((void**)&x2,  g_x2);

    // fork sW: qkv weight FIRST (unblocks the first GEMM asap), then the rest
    cudaEventRecord(evF1, 0);
    cudaStreamWaitEvent(sW, evF1, 0);
    f2h_kernel<<<(DD*3*DD/8 + 255)/256, 256, 0, sW>>>(qkv_w, wq, DD*3*DD/8);
    cudaEventRecord(evWq, sW);
    f2h_kernel<<<(DD*DD/8   + 255)/256, 256, 0, sW>>>(proj_w, wp, DD*DD/8);
    f2h_kernel<<<(DD*SHH/8  + 255)/256, 256, 0, sW>>>(sh_w1, w1, DD*SHH/8);
    f2h_kernel<<<(SHH*DD/8  + 255)/256, 256, 0, sW>>>(sh_w2, w2, SHH*DD/8);
    cudaEventRecord(evW, sW);
    expconv_kernel<<<dim3(2*DD*HID/8/256, EE), 256, 0, sW>>>(exp_w1, exp_w2);
    cudaEventRecord(evWX, sW);

    // attention branch (main stream)
    ln_kernel<<<NTOK, 256>>>(x, ln1_g, ln1_b, h1h);
    cudaStreamWaitEvent(0, evWq, 0);
    qkv_g2<<<dim3(18, 32), 128, SMEMB_G2>>>();
    flash_tc<<<dim3(4, BHN), 256, FLASH_SMEM>>>();
    cudaStreamWaitEvent(0, evW, 0);
    proj_g2<<<dim3(6, 32), 128, SMEMB_G2>>>(proj_b, x);

    // ln2 -> fork shared-expert chain onto sB
    ln_kernel<<<NTOK, 256>>>(x2, ln2_g, ln2_b, h2h);
    cudaEventRecord(evF2, 0);
    cudaStreamWaitEvent(sB, evF2, 0);
    cudaStreamWaitEvent(sB, evW, 0);
    shared_hid_g2<<<dim3(24, 32), 128, SMEMB_G2, sB>>>(sh_b1);
    final_split_g2<<<dim3(6, 32, 2), 128, SMEMB_G2, sB>>>();
    cudaEventRecord(evB, sB);

    // routed-expert chain (main stream, overlaps sB)
    router_kernel<<<BB, 1024>>>(router_w1, router_b1, router_w2, router_b2);
    cudaStreamWaitEvent(0, evWX, 0);
    expert_hid_g2<<<dim3(12, 4, BB * KK), 128, SMEMB_G2>>>(exp_b1);
    expert_out_g2<<<dim3(6, 4, BB * KK), 128, SMEMB_G2>>>(exp_b2);

    // join and reduce
    cudaStreamWaitEvent(0, evB, 0);
    final_sum_kernel<<<NTOK * DD / 4 / 256, 256>>>(sh_b2, out);
}